// round 1
// baseline (speedup 1.0000x reference)
#include <cuda_runtime.h>
#include <math.h>

// ---------------------------------------------------------------------------
// attention_83932250898666 : B=4, N=2048, D=1024
// out layout in d_out (float32):
//   [0, 16777216)        out   = concat(x, LN(x+att))   [B,N,2D]
//   [16777216, 25165824) att_score                      [B,N,D]
//   [25165824, 41943040) weight = softmax(QK^T/32)      [B,N,N]
// ---------------------------------------------------------------------------

#define Bb 4
#define Nn 2048
#define Dd 1024

// scratch for Q,K,V (allocation-free rule -> __device__ globals)
__device__ float g_Q[(long long)Bb * Nn * Dd];
__device__ float g_K[(long long)Bb * Nn * Dd];
__device__ float g_V[(long long)Bb * Nn * Dd];

#define BM 128
#define BN 128
#define BK 16
#define TM 8
#define TN 8
#define PAD 4

// C[M,N] = alpha * A[M,K] @ B(KxN or (NxK)^T) (+bias), batched by blockIdx.z
template <bool TRANSB, bool HAS_BIAS>
__global__ __launch_bounds__(256, 2)
void sgemm_kernel(const float* __restrict__ A, const float* __restrict__ B,
                  const float* __restrict__ bias, float* __restrict__ C,
                  int M, int N, int K,
                  long long sA, long long sB, long long sC, float alpha)
{
    A += (long long)blockIdx.z * sA;
    B += (long long)blockIdx.z * sB;
    C += (long long)blockIdx.z * sC;

    __shared__ float As[BK][BM + PAD];
    __shared__ float Bs[BK][BN + PAD];

    const int tid = threadIdx.x;          // 256 threads
    const int tx  = tid & 15;             // -> n direction
    const int ty  = tid >> 4;             // -> m direction
    const int m0  = blockIdx.y * BM;
    const int n0  = blockIdx.x * BN;

    float acc[TM][TN];
#pragma unroll
    for (int i = 0; i < TM; i++)
#pragma unroll
        for (int j = 0; j < TN; j++) acc[i][j] = 0.0f;

    for (int k0 = 0; k0 < K; k0 += BK) {
        // ---- load A tile (BM x BK) transposed into As[k][m] ----
        // 128 rows x 4 float4 = 512 float4, 2 per thread
#pragma unroll
        for (int i = 0; i < 2; i++) {
            int idx = tid + i * 256;           // 0..511
            int r   = idx >> 2;                // row in tile 0..127
            int c4  = idx & 3;                 // which float4 along k
            float4 v = *reinterpret_cast<const float4*>(
                &A[(long long)(m0 + r) * K + k0 + c4 * 4]);
            As[c4 * 4 + 0][r] = v.x;
            As[c4 * 4 + 1][r] = v.y;
            As[c4 * 4 + 2][r] = v.z;
            As[c4 * 4 + 3][r] = v.w;
        }
        if (!TRANSB) {
            // B row-major K x N ; Bs[k][n]
#pragma unroll
            for (int i = 0; i < 2; i++) {
                int idx = tid + i * 256;       // 0..511
                int r   = idx >> 5;            // k row 0..15
                int c4  = idx & 31;            // float4 along n
                float4 v = *reinterpret_cast<const float4*>(
                    &B[(long long)(k0 + r) * N + n0 + c4 * 4]);
                *reinterpret_cast<float4*>(&Bs[r][c4 * 4]) = v;
            }
        } else {
            // B is N x K ; Bs[k][n] = B[n0+n][k0+k]
#pragma unroll
            for (int i = 0; i < 2; i++) {
                int idx = tid + i * 256;
                int r   = idx >> 2;            // n 0..127
                int c4  = idx & 3;             // float4 along k
                float4 v = *reinterpret_cast<const float4*>(
                    &B[(long long)(n0 + r) * K + k0 + c4 * 4]);
                Bs[c4 * 4 + 0][r] = v.x;
                Bs[c4 * 4 + 1][r] = v.y;
                Bs[c4 * 4 + 2][r] = v.z;
                Bs[c4 * 4 + 3][r] = v.w;
            }
        }
        __syncthreads();

#pragma unroll
        for (int k = 0; k < BK; k++) {
            float a[TM], b[TN];
            float4 a0 = *reinterpret_cast<const float4*>(&As[k][ty * TM]);
            float4 a1 = *reinterpret_cast<const float4*>(&As[k][ty * TM + 4]);
            float4 b0 = *reinterpret_cast<const float4*>(&Bs[k][tx * TN]);
            float4 b1 = *reinterpret_cast<const float4*>(&Bs[k][tx * TN + 4]);
            a[0]=a0.x; a[1]=a0.y; a[2]=a0.z; a[3]=a0.w;
            a[4]=a1.x; a[5]=a1.y; a[6]=a1.z; a[7]=a1.w;
            b[0]=b0.x; b[1]=b0.y; b[2]=b0.z; b[3]=b0.w;
            b[4]=b1.x; b[5]=b1.y; b[6]=b1.z; b[7]=b1.w;
#pragma unroll
            for (int i = 0; i < TM; i++)
#pragma unroll
                for (int j = 0; j < TN; j++)
                    acc[i][j] = fmaf(a[i], b[j], acc[i][j]);
        }
        __syncthreads();
    }

#pragma unroll
    for (int i = 0; i < TM; i++) {
        long long m = m0 + ty * TM + i;
#pragma unroll
        for (int j = 0; j < TN; j += 4) {
            int n = n0 + tx * TN + j;
            float4 v;
            v.x = acc[i][j + 0] * alpha;
            v.y = acc[i][j + 1] * alpha;
            v.z = acc[i][j + 2] * alpha;
            v.w = acc[i][j + 3] * alpha;
            if (HAS_BIAS) {
                v.x += bias[n + 0]; v.y += bias[n + 1];
                v.z += bias[n + 2]; v.w += bias[n + 3];
            }
            *reinterpret_cast<float4*>(&C[m * N + n]) = v;
        }
    }
}

// in-place row softmax, one block per row
__global__ void softmax_rows(float* __restrict__ W, int ncols)
{
    long long row = blockIdx.x;
    float* p = W + row * (long long)ncols;
    __shared__ float red[256];
    int tid = threadIdx.x;

    float mx = -INFINITY;
    for (int c = tid; c < ncols; c += 256) mx = fmaxf(mx, p[c]);
    red[tid] = mx; __syncthreads();
#pragma unroll
    for (int s = 128; s > 0; s >>= 1) {
        if (tid < s) red[tid] = fmaxf(red[tid], red[tid + s]);
        __syncthreads();
    }
    mx = red[0];
    __syncthreads();

    float sum = 0.0f;
    for (int c = tid; c < ncols; c += 256) {
        float e = expf(p[c] - mx);
        p[c] = e;
        sum += e;
    }
    red[tid] = sum; __syncthreads();
#pragma unroll
    for (int s = 128; s > 0; s >>= 1) {
        if (tid < s) red[tid] += red[tid + s];
        __syncthreads();
    }
    float inv = 1.0f / red[0];
    for (int c = tid; c < ncols; c += 256) p[c] *= inv;
}

// residual + layernorm + concat(x, ln) ; one block per (b,n) row, 256 threads
__global__ void ln_concat(const float* __restrict__ x, const float* __restrict__ att,
                          const float* __restrict__ gamma, const float* __restrict__ beta,
                          float* __restrict__ out)
{
    long long row = blockIdx.x;
    const float* xr = x + row * Dd;
    const float* ar = att + row * Dd;
    float* o = out + row * (2 * Dd);
    __shared__ float red[256];
    int tid = threadIdx.x;

    float h[4];
    float s = 0.0f;
#pragma unroll
    for (int i = 0; i < 4; i++) {
        int c = tid + i * 256;
        h[i] = xr[c] + ar[c];
        s += h[i];
    }
    red[tid] = s; __syncthreads();
#pragma unroll
    for (int st = 128; st > 0; st >>= 1) {
        if (tid < st) red[tid] += red[tid + st];
        __syncthreads();
    }
    float mu = red[0] * (1.0f / Dd);
    __syncthreads();

    float v = 0.0f;
#pragma unroll
    for (int i = 0; i < 4; i++) { float d = h[i] - mu; v += d * d; }
    red[tid] = v; __syncthreads();
#pragma unroll
    for (int st = 128; st > 0; st >>= 1) {
        if (tid < st) red[tid] += red[tid + st];
        __syncthreads();
    }
    float rstd = rsqrtf(red[0] * (1.0f / Dd) + 1e-5f);

#pragma unroll
    for (int i = 0; i < 4; i++) {
        int c = tid + i * 256;
        o[c]       = xr[c];
        o[Dd + c]  = (h[i] - mu) * rstd * gamma[c] + beta[c];
    }
}

extern "C" void kernel_launch(void* const* d_in, const int* in_sizes, int n_in,
                              void* d_out, int out_size)
{
    const float* x     = (const float*)d_in[0];
    const float* Wk    = (const float*)d_in[1];
    const float* bk    = (const float*)d_in[2];
    const float* Wq    = (const float*)d_in[3];
    const float* bq    = (const float*)d_in[4];
    const float* Wv    = (const float*)d_in[5];
    const float* bv    = (const float*)d_in[6];
    const float* gamma = (const float*)d_in[7];
    const float* beta  = (const float*)d_in[8];

    float* out = (float*)d_out;                       // [B,N,2D]
    float* att = out + (long long)Bb * Nn * 2 * Dd;   // [B,N,D]
    float* wgt = att + (long long)Bb * Nn * Dd;       // [B,N,N]

    float *Q, *K, *V;
    cudaGetSymbolAddress((void**)&Q, g_Q);
    cudaGetSymbolAddress((void**)&K, g_K);
    cudaGetSymbolAddress((void**)&V, g_V);

    const long long sQKV = (long long)Nn * Dd;   // per-batch stride of Q/K/V/att
    const long long sW   = (long long)Nn * Nn;   // per-batch stride of weight

    dim3 blk(256);

    // 1) QKV projections: [8192,1024] x [1024,1024] (+bias)
    {
        dim3 grid(Dd / BN, (Bb * Nn) / BM, 1);
        sgemm_kernel<false, true><<<grid, blk>>>(x, Wq, bq, Q, Bb * Nn, Dd, Dd, 0, 0, 0, 1.0f);
        sgemm_kernel<false, true><<<grid, blk>>>(x, Wk, bk, K, Bb * Nn, Dd, Dd, 0, 0, 0, 1.0f);
        sgemm_kernel<false, true><<<grid, blk>>>(x, Wv, bv, V, Bb * Nn, Dd, Dd, 0, 0, 0, 1.0f);
    }

    // 2) scores = Q @ K^T / 32 -> weight region (batched)
    {
        dim3 grid(Nn / BN, Nn / BM, Bb);
        sgemm_kernel<true, false><<<grid, blk>>>(Q, K, nullptr, wgt,
                                                 Nn, Nn, Dd, sQKV, sQKV, sW,
                                                 1.0f / 32.0f);
    }

    // 3) softmax rows in place
    softmax_rows<<<Bb * Nn, blk>>>(wgt, Nn);

    // 4) att = weight @ V -> att region (batched)
    {
        dim3 grid(Dd / BN, Nn / BM, Bb);
        sgemm_kernel<false, false><<<grid, blk>>>(wgt, V, nullptr, att,
                                                  Nn, Dd, Nn, sW, sQKV, sQKV,
                                                  1.0f);
    }

    // 5) out = concat(x, LN(x + att))
    ln_concat<<<Bb * Nn, blk>>>(x, att, gamma, beta, out);
}

// round 3
// speedup vs baseline: 2.0777x; 2.0777x over previous
#include <cuda_runtime.h>
#include <cuda_bf16.h>
#include <math.h>
#include <stdint.h>

// ---------------------------------------------------------------------------
// attention_83932250898666 : B=4, N=2048, D=1024
// d_out layout (float32):
//   [0, 16777216)        out   = concat(x, LN(x+att))   [B,N,2D]
//   [16777216, 25165824) att_score                      [B,N,D]
//   [25165824, 41943040) weight = softmax(QK^T/32)      [B,N,N]
// GEMMs: mma.sync bf16 (HMMA) with 2-term bf16 split, 3 passes, fp32 acc.
// ---------------------------------------------------------------------------

#define Bb 4
#define Nn 2048
#define Dd 1024
#define MT (Bb*Nn)   // 8192

// ------------------------- device scratch (no allocs) ----------------------
__device__ __nv_bfloat16 g_xh[(size_t)MT*Dd], g_xl[(size_t)MT*Dd];
__device__ __nv_bfloat16 g_Wqh[(size_t)Dd*Dd], g_Wql[(size_t)Dd*Dd];
__device__ __nv_bfloat16 g_Wkh[(size_t)Dd*Dd], g_Wkl[(size_t)Dd*Dd];
__device__ __nv_bfloat16 g_Wvh[(size_t)Dd*Dd], g_Wvl[(size_t)Dd*Dd];
__device__ __nv_bfloat16 g_Qh[(size_t)MT*Dd],  g_Ql[(size_t)MT*Dd];
__device__ __nv_bfloat16 g_Kh[(size_t)MT*Dd],  g_Kl[(size_t)MT*Dd];
__device__ __nv_bfloat16 g_Vh[(size_t)MT*Dd],  g_Vl[(size_t)MT*Dd];   // [b*n, d]
__device__ __nv_bfloat16 g_Vth[(size_t)MT*Dd], g_Vtl[(size_t)MT*Dd];  // [b][d][n]
__device__ __nv_bfloat16 g_wh[(size_t)Bb*Nn*Nn], g_wl[(size_t)Bb*Nn*Nn];

// ------------------------------ PTX helpers --------------------------------
__device__ __forceinline__ uint32_t smem_u32(const void* p) {
    uint32_t a;
    asm("{ .reg .u64 t; cvta.to.shared.u64 t, %1; cvt.u32.u64 %0, t; }" : "=r"(a) : "l"(p));
    return a;
}

#define CP16(dst, src) \
    asm volatile("cp.async.cg.shared.global [%0], [%1], 16;" :: "r"(dst), "l"(src))
#define CP_COMMIT() asm volatile("cp.async.commit_group;" ::: "memory")
#define CP_WAIT1()  asm volatile("cp.async.wait_group 1;" ::: "memory")

#define LDSM4(R0, R1, R2, R3, A) \
    asm volatile("ldmatrix.sync.aligned.m8n8.x4.shared.b16 {%0,%1,%2,%3}, [%4];" \
                 : "=r"(R0), "=r"(R1), "=r"(R2), "=r"(R3) : "r"(A))

#define MMA(D, A, B0, B1) \
    asm volatile("mma.sync.aligned.m16n8k16.row.col.f32.bf16.bf16.f32 " \
                 "{%0,%1,%2,%3},{%4,%5,%6,%7},{%8,%9},{%0,%1,%2,%3};" \
                 : "+f"((D)[0]), "+f"((D)[1]), "+f"((D)[2]), "+f"((D)[3]) \
                 : "r"((A)[0]), "r"((A)[1]), "r"((A)[2]), "r"((A)[3]), "r"(B0), "r"(B1))

// ------------------------------- MMA GEMM ----------------------------------
// C[M,N] = alpha * (A @ Bmat^T) (+bias). A:[M,K] hi/lo bf16 (ld=K),
// Bmat:[N,K] hi/lo bf16 (ld=K). Block 128x128, K-chunk 32, 3-stage cp.async.
#define BMm 128
#define BNm 128
#define BKm 32
#define LDSm 40                         // padded row length in bf16
#define OPB (128 * LDSm * 2)            // bytes per operand tile (10240)
#define STGB (4 * OPB)                  // bytes per stage (40960)
#define NSTAGE 3
#define SMEM_BYTES (NSTAGE * STGB)      // 122880

template<int EPI, bool BIAS>   // EPI 0: fp32 out ; EPI 1: bf16 hi/lo out (+bias)
__global__ __launch_bounds__(256, 1)
void mma_gemm(const __nv_bfloat16* __restrict__ Ah, const __nv_bfloat16* __restrict__ Al,
              const __nv_bfloat16* __restrict__ Bh, const __nv_bfloat16* __restrict__ Bl,
              const float* __restrict__ bias,
              float* __restrict__ Cf, __nv_bfloat16* __restrict__ Ch, __nv_bfloat16* __restrict__ Cl,
              int K, int ldc,
              long long sA, long long sB, long long sC, float alpha)
{
    extern __shared__ char smem[];
    const uint32_t sbase = smem_u32(smem);
    const int tid  = threadIdx.x;
    const int wid  = tid >> 5;
    const int lane = tid & 31;
    const int wy = wid >> 1;            // 0..3  (m)
    const int wx = wid & 1;             // 0..1  (n)
    const int m0 = blockIdx.y * BMm;
    const int n0 = blockIdx.x * BNm;
    Ah += blockIdx.z * sA; Al += blockIdx.z * sA;
    Bh += blockIdx.z * sB; Bl += blockIdx.z * sB;

    // per-thread cp.async chunk coords (2 chunks per operand per stage)
    const int r0c = tid >> 2,          c0c = tid & 3;          // chunk 0
    const int r1c = (tid + 256) >> 2,  c1c = tid & 3;          // chunk 1

    float acc[2][8][4];
#pragma unroll
    for (int i = 0; i < 2; i++)
#pragma unroll
        for (int j = 0; j < 8; j++)
#pragma unroll
            for (int q = 0; q < 4; q++) acc[i][j][q] = 0.0f;

    const int nch = K / BKm;

    auto load_stage = [&](int s, int k0) {
        uint32_t sb = sbase + s * STGB;
        // A hi/lo
        CP16(sb + (uint32_t)(r0c * LDSm + c0c * 8) * 2,
             Ah + (long long)(m0 + r0c) * K + k0 + c0c * 8);
        CP16(sb + (uint32_t)(r1c * LDSm + c1c * 8) * 2,
             Ah + (long long)(m0 + r1c) * K + k0 + c1c * 8);
        CP16(sb + OPB + (uint32_t)(r0c * LDSm + c0c * 8) * 2,
             Al + (long long)(m0 + r0c) * K + k0 + c0c * 8);
        CP16(sb + OPB + (uint32_t)(r1c * LDSm + c1c * 8) * 2,
             Al + (long long)(m0 + r1c) * K + k0 + c1c * 8);
        // B hi/lo
        CP16(sb + 2 * OPB + (uint32_t)(r0c * LDSm + c0c * 8) * 2,
             Bh + (long long)(n0 + r0c) * K + k0 + c0c * 8);
        CP16(sb + 2 * OPB + (uint32_t)(r1c * LDSm + c1c * 8) * 2,
             Bh + (long long)(n0 + r1c) * K + k0 + c1c * 8);
        CP16(sb + 3 * OPB + (uint32_t)(r0c * LDSm + c0c * 8) * 2,
             Bl + (long long)(n0 + r0c) * K + k0 + c0c * 8);
        CP16(sb + 3 * OPB + (uint32_t)(r1c * LDSm + c1c * 8) * 2,
             Bl + (long long)(n0 + r1c) * K + k0 + c1c * 8);
    };

    load_stage(0, 0);       CP_COMMIT();
    load_stage(1, BKm);     CP_COMMIT();

    // ldmatrix lane address components
    const int arow  = (lane & 7) + ((lane >> 3) & 1) * 8;   // 0..15
    const int acol  = (lane >> 4) * 8;                      // 0 / 8
    const int brow  = (lane & 7) + (lane >> 4) * 8;         // within 16-row pair
    const int bcol  = ((lane >> 3) & 1) * 8;                // 0 / 8

    for (int c = 0; c < nch; c++) {
        CP_WAIT1();
        __syncthreads();
        if (c + 2 < nch) load_stage((c + 2) % NSTAGE, (c + 2) * BKm);
        CP_COMMIT();

        const uint32_t sb = sbase + (c % NSTAGE) * STGB;
#pragma unroll
        for (int ks = 0; ks < 2; ks++) {
            uint32_t af_h[2][4], af_l[2][4];
#pragma unroll
            for (int i = 0; i < 2; i++) {
                uint32_t aoff = (uint32_t)((32 * wy + 16 * i + arow) * LDSm
                                           + ks * 16 + acol) * 2;
                LDSM4(af_h[i][0], af_h[i][1], af_h[i][2], af_h[i][3], sb + aoff);
                LDSM4(af_l[i][0], af_l[i][1], af_l[i][2], af_l[i][3], sb + OPB + aoff);
            }
            uint32_t bh[8][2], bl[8][2];
#pragma unroll
            for (int jp = 0; jp < 4; jp++) {
                uint32_t boff = (uint32_t)((64 * wx + 16 * jp + brow) * LDSm
                                           + ks * 16 + bcol) * 2;
                LDSM4(bh[2*jp][0], bh[2*jp][1], bh[2*jp+1][0], bh[2*jp+1][1],
                      sb + 2 * OPB + boff);
                LDSM4(bl[2*jp][0], bl[2*jp][1], bl[2*jp+1][0], bl[2*jp+1][1],
                      sb + 3 * OPB + boff);
            }
#pragma unroll
            for (int i = 0; i < 2; i++)
#pragma unroll
                for (int j = 0; j < 8; j++) {
                    MMA(acc[i][j], af_h[i], bh[j][0], bh[j][1]);
                    MMA(acc[i][j], af_h[i], bl[j][0], bl[j][1]);
                    MMA(acc[i][j], af_l[i], bh[j][0], bh[j][1]);
                }
        }
        __syncthreads();
    }

    // ------------------------------ epilogue --------------------------------
    const int g  = lane >> 2;
    const int t4 = lane & 3;
    const long long cb = (long long)blockIdx.z * sC;
#pragma unroll
    for (int i = 0; i < 2; i++) {
#pragma unroll
        for (int j = 0; j < 8; j++) {
            int mrow = m0 + 32 * wy + 16 * i + g;
            int ncol = n0 + 64 * wx + 8 * j + 2 * t4;
            float v00 = acc[i][j][0] * alpha, v01 = acc[i][j][1] * alpha;
            float v10 = acc[i][j][2] * alpha, v11 = acc[i][j][3] * alpha;
            if (EPI == 0) {
                float2 p0 = make_float2(v00, v01);
                float2 p1 = make_float2(v10, v11);
                *(float2*)(Cf + cb + (long long)mrow * ldc + ncol) = p0;
                *(float2*)(Cf + cb + (long long)(mrow + 8) * ldc + ncol) = p1;
            } else {
                if (BIAS) {
                    float b0 = bias[ncol], b1 = bias[ncol + 1];
                    v00 += b0; v01 += b1; v10 += b0; v11 += b1;
                }
                __nv_bfloat162 h0, h1, l0, l1;
                h0.x = __float2bfloat16(v00); h0.y = __float2bfloat16(v01);
                h1.x = __float2bfloat16(v10); h1.y = __float2bfloat16(v11);
                l0.x = __float2bfloat16(v00 - __bfloat162float(h0.x));
                l0.y = __float2bfloat16(v01 - __bfloat162float(h0.y));
                l1.x = __float2bfloat16(v10 - __bfloat162float(h1.x));
                l1.y = __float2bfloat16(v11 - __bfloat162float(h1.y));
                long long o0 = cb + (long long)mrow * ldc + ncol;
                long long o1 = cb + (long long)(mrow + 8) * ldc + ncol;
                *(__nv_bfloat162*)(Ch + o0) = h0;
                *(__nv_bfloat162*)(Ch + o1) = h1;
                *(__nv_bfloat162*)(Cl + o0) = l0;
                *(__nv_bfloat162*)(Cl + o1) = l1;
            }
        }
    }
}

// --------------------------- aux kernels ------------------------------------
__global__ void split_f32(const float* __restrict__ in, __nv_bfloat16* __restrict__ oh,
                          __nv_bfloat16* __restrict__ ol)
{
    long long i = (long long)blockIdx.x * blockDim.x + threadIdx.x;
    float v = in[i];
    __nv_bfloat16 h = __float2bfloat16(v);
    oh[i] = h;
    ol[i] = __float2bfloat16(v - __bfloat162float(h));
}

// out[n,k] = W[k,n], split to hi/lo.  W: 1024x1024 fp32
__global__ void transW(const float* __restrict__ W, __nv_bfloat16* __restrict__ oh,
                       __nv_bfloat16* __restrict__ ol)
{
    __shared__ float t[32][33];
    int bx = blockIdx.x * 32, by = blockIdx.y * 32;
    int tx = threadIdx.x, ty = threadIdx.y;
#pragma unroll
    for (int r = 0; r < 4; r++)
        t[ty + 8 * r][tx] = W[(long long)(by + ty + 8 * r) * Dd + bx + tx];
    __syncthreads();
#pragma unroll
    for (int r = 0; r < 4; r++) {
        float v = t[tx][ty + 8 * r];
        __nv_bfloat16 h = __float2bfloat16(v);
        long long o = (long long)(bx + ty + 8 * r) * Dd + by + tx;
        oh[o] = h;
        ol[o] = __float2bfloat16(v - __bfloat162float(h));
    }
}

// per-batch transpose of bf16 hi/lo: in [2048,1024] -> out [1024,2048]
__global__ void transV(const __nv_bfloat16* __restrict__ ih, const __nv_bfloat16* __restrict__ il,
                       __nv_bfloat16* __restrict__ oh, __nv_bfloat16* __restrict__ ol)
{
    __shared__ __nv_bfloat16 th[32][34], tl[32][34];
    long long zi = (long long)blockIdx.z * Nn * Dd;
    int bx = blockIdx.x * 32, by = blockIdx.y * 32;
    int tx = threadIdx.x, ty = threadIdx.y;
#pragma unroll
    for (int r = 0; r < 4; r++) {
        long long s = zi + (long long)(by + ty + 8 * r) * Dd + bx + tx;
        th[ty + 8 * r][tx] = ih[s];
        tl[ty + 8 * r][tx] = il[s];
    }
    __syncthreads();
#pragma unroll
    for (int r = 0; r < 4; r++) {
        long long o = zi + (long long)(bx + ty + 8 * r) * Nn + by + tx;
        oh[o] = th[tx][ty + 8 * r];
        ol[o] = tl[tx][ty + 8 * r];
    }
}

// in-place row softmax + bf16 hi/lo emission
__global__ void softmax_split(float* __restrict__ W, __nv_bfloat16* __restrict__ wh,
                              __nv_bfloat16* __restrict__ wl)
{
    long long row = blockIdx.x;
    float* p = W + row * (long long)Nn;
    __nv_bfloat16* ph = wh + row * (long long)Nn;
    __nv_bfloat16* pl = wl + row * (long long)Nn;
    __shared__ float red[256];
    int tid = threadIdx.x;

    float mx = -INFINITY;
#pragma unroll
    for (int i = 0; i < 8; i++) mx = fmaxf(mx, p[tid + i * 256]);
    red[tid] = mx; __syncthreads();
#pragma unroll
    for (int s = 128; s > 0; s >>= 1) {
        if (tid < s) red[tid] = fmaxf(red[tid], red[tid + s]);
        __syncthreads();
    }
    mx = red[0]; __syncthreads();

    float e[8], sum = 0.0f;
#pragma unroll
    for (int i = 0; i < 8; i++) { e[i] = expf(p[tid + i * 256] - mx); sum += e[i]; }
    red[tid] = sum; __syncthreads();
#pragma unroll
    for (int s = 128; s > 0; s >>= 1) {
        if (tid < s) red[tid] += red[tid + s];
        __syncthreads();
    }
    float inv = 1.0f / red[0];
#pragma unroll
    for (int i = 0; i < 8; i++) {
        int c = tid + i * 256;
        float v = e[i] * inv;
        p[c] = v;
        __nv_bfloat16 h = __float2bfloat16(v);
        ph[c] = h;
        pl[c] = __float2bfloat16(v - __bfloat162float(h));
    }
}

// residual + layernorm + concat(x, ln)
__global__ void ln_concat(const float* __restrict__ x, const float* __restrict__ att,
                          const float* __restrict__ gamma, const float* __restrict__ beta,
                          float* __restrict__ out)
{
    long long row = blockIdx.x;
    const float* xr = x + row * Dd;
    const float* ar = att + row * Dd;
    float* o = out + row * (2 * Dd);
    __shared__ float red[256];
    int tid = threadIdx.x;

    float h[4], s = 0.0f;
#pragma unroll
    for (int i = 0; i < 4; i++) { int c = tid + i * 256; h[i] = xr[c] + ar[c]; s += h[i]; }
    red[tid] = s; __syncthreads();
#pragma unroll
    for (int st = 128; st > 0; st >>= 1) {
        if (tid < st) red[tid] += red[tid + st];
        __syncthreads();
    }
    float mu = red[0] * (1.0f / Dd); __syncthreads();

    float v = 0.0f;
#pragma unroll
    for (int i = 0; i < 4; i++) { float d = h[i] - mu; v += d * d; }
    red[tid] = v; __syncthreads();
#pragma unroll
    for (int st = 128; st > 0; st >>= 1) {
        if (tid < st) red[tid] += red[tid + st];
        __syncthreads();
    }
    float rstd = rsqrtf(red[0] * (1.0f / Dd) + 1e-5f);
#pragma unroll
    for (int i = 0; i < 4; i++) {
        int c = tid + i * 256;
        o[c]      = xr[c];
        o[Dd + c] = (h[i] - mu) * rstd * gamma[c] + beta[c];
    }
}

// ------------------------------- launcher -----------------------------------
extern "C" void kernel_launch(void* const* d_in, const int* in_sizes, int n_in,
                              void* d_out, int out_size)
{
    const float* x     = (const float*)d_in[0];
    const float* Wk    = (const float*)d_in[1];
    const float* bk    = (const float*)d_in[2];
    const float* Wq    = (const float*)d_in[3];
    const float* bq    = (const float*)d_in[4];
    const float* Wv    = (const float*)d_in[5];
    const float* bv    = (const float*)d_in[6];
    const float* gamma = (const float*)d_in[7];
    const float* beta  = (const float*)d_in[8];

    float* out = (float*)d_out;
    float* att = out + (long long)MT * 2 * Dd;
    float* wgt = att + (long long)MT * Dd;

    __nv_bfloat16 *xh, *xl, *Wqh, *Wql, *Wkh, *Wkl, *Wvh, *Wvl;
    __nv_bfloat16 *Qh, *Ql, *Kh, *Kl, *Vh, *Vl, *Vth, *Vtl, *wh, *wl;
    cudaGetSymbolAddress((void**)&xh,  g_xh);  cudaGetSymbolAddress((void**)&xl,  g_xl);
    cudaGetSymbolAddress((void**)&Wqh, g_Wqh); cudaGetSymbolAddress((void**)&Wql, g_Wql);
    cudaGetSymbolAddress((void**)&Wkh, g_Wkh); cudaGetSymbolAddress((void**)&Wkl, g_Wkl);
    cudaGetSymbolAddress((void**)&Wvh, g_Wvh); cudaGetSymbolAddress((void**)&Wvl, g_Wvl);
    cudaGetSymbolAddress((void**)&Qh,  g_Qh);  cudaGetSymbolAddress((void**)&Ql,  g_Ql);
    cudaGetSymbolAddress((void**)&Kh,  g_Kh);  cudaGetSymbolAddress((void**)&Kl,  g_Kl);
    cudaGetSymbolAddress((void**)&Vh,  g_Vh);  cudaGetSymbolAddress((void**)&Vl,  g_Vl);
    cudaGetSymbolAddress((void**)&Vth, g_Vth); cudaGetSymbolAddress((void**)&Vtl, g_Vtl);
    cudaGetSymbolAddress((void**)&wh,  g_wh);  cudaGetSymbolAddress((void**)&wl,  g_wl);

    cudaFuncSetAttribute(mma_gemm<0, false>, cudaFuncAttributeMaxDynamicSharedMemorySize, SMEM_BYTES);
    cudaFuncSetAttribute(mma_gemm<1, true>,  cudaFuncAttributeMaxDynamicSharedMemorySize, SMEM_BYTES);

    // 1) split x ; transpose+split weights
    split_f32<<<MT * Dd / 1024, 1024>>>(x, xh, xl);
    {
        dim3 g(Dd / 32, Dd / 32), b(32, 8);
        transW<<<g, b>>>(Wq, Wqh, Wql);
        transW<<<g, b>>>(Wk, Wkh, Wkl);
        transW<<<g, b>>>(Wv, Wvh, Wvl);
    }

    // 2) projections: [8192,1024] @ Wt[1024,1024]^T + bias -> split bf16
    {
        dim3 g(Dd / BNm, MT / BMm, 1), b(256);
        mma_gemm<1, true><<<g, b, SMEM_BYTES>>>(xh, xl, Wqh, Wql, bq, nullptr, Qh, Ql,
                                                Dd, Dd, 0, 0, 0, 1.0f);
        mma_gemm<1, true><<<g, b, SMEM_BYTES>>>(xh, xl, Wkh, Wkl, bk, nullptr, Kh, Kl,
                                                Dd, Dd, 0, 0, 0, 1.0f);
        mma_gemm<1, true><<<g, b, SMEM_BYTES>>>(xh, xl, Wvh, Wvl, bv, nullptr, Vh, Vl,
                                                Dd, Dd, 0, 0, 0, 1.0f);
    }

    // 3) V transpose per batch: [n,d] -> [d,n]
    {
        dim3 g(Dd / 32, Nn / 32, Bb), b(32, 8);
        transV<<<g, b>>>(Vh, Vl, Vth, Vtl);
    }

    // 4) scores = Q @ K^T / 32 -> wgt (fp32)
    {
        dim3 g(Nn / BNm, Nn / BMm, Bb), b(256);
        mma_gemm<0, false><<<g, b, SMEM_BYTES>>>(Qh, Ql, Kh, Kl, nullptr, wgt, nullptr, nullptr,
                                                 Dd, Nn,
                                                 (long long)Nn * Dd, (long long)Nn * Dd,
                                                 (long long)Nn * Nn, 1.0f / 32.0f);
    }

    // 5) softmax rows in place + bf16 split
    softmax_split<<<Bb * Nn, 256>>>(wgt, wh, wl);

    // 6) att = weight @ V -> att (fp32)
    {
        dim3 g(Dd / BNm, Nn / BMm, Bb), b(256);
        mma_gemm<0, false><<<g, b, SMEM_BYTES>>>(wh, wl, Vth, Vtl, nullptr, att, nullptr, nullptr,
                                                 Nn, Dd,
                                                 (long long)Nn * Nn, (long long)Nn * Dd,
                                                 (long long)Nn * Dd, 1.0f);
    }

    // 7) out = concat(x, LN(x + att))
    ln_concat<<<Bb * Nn, 256>>>(x, att, gamma, beta, out);
}

// round 4
// speedup vs baseline: 4.9155x; 2.3659x over previous
#include <cuda_runtime.h>
#include <cuda_fp16.h>
#include <math.h>
#include <stdint.h>

// ---------------------------------------------------------------------------
// attention_83932250898666 : B=4, N=2048, D=1024
// d_out layout (float32):
//   [0, 16777216)        out   = concat(x, LN(x+att))   [B,N,2D]
//   [16777216, 25165824) att_score                      [B,N,D]
//   [25165824, 41943040) weight = softmax(QK^T/32)      [B,N,N]
// GEMMs: single-pass fp16 mma.sync (HMMA), fp32 accumulate.
// ---------------------------------------------------------------------------

#define Bb 4
#define Nn 2048
#define Dd 1024
#define MT (Bb*Nn)   // 8192

// ------------------------- device scratch (no allocs) ----------------------
__device__ __half g_x16[(size_t)MT * Dd];
__device__ __half g_W16[(size_t)3 * Dd * Dd];      // [z][n][k] transposed weights
__device__ float  g_b[3 * Dd];                     // biases q,k,v
__device__ __half g_QKV[(size_t)3 * MT * Dd];      // Q | K | V
__device__ __half g_Vt[(size_t)MT * Dd];           // per-batch V^T [b][d][n]
__device__ __half g_w16[(size_t)Bb * Nn * Nn];     // softmax weights fp16

// ------------------------------ PTX helpers --------------------------------
__device__ __forceinline__ uint32_t smem_u32(const void* p) {
    uint32_t a;
    asm("{ .reg .u64 t; cvta.to.shared.u64 t, %1; cvt.u32.u64 %0, t; }" : "=r"(a) : "l"(p));
    return a;
}

#define CP16(dst, src) \
    asm volatile("cp.async.cg.shared.global [%0], [%1], 16;" :: "r"(dst), "l"(src))
#define CP_COMMIT() asm volatile("cp.async.commit_group;" ::: "memory")
#define CP_WAIT1()  asm volatile("cp.async.wait_group 1;" ::: "memory")

#define LDSM4(R0, R1, R2, R3, A) \
    asm volatile("ldmatrix.sync.aligned.m8n8.x4.shared.b16 {%0,%1,%2,%3}, [%4];" \
                 : "=r"(R0), "=r"(R1), "=r"(R2), "=r"(R3) : "r"(A))

#define MMAH(D, A, B0, B1) \
    asm volatile("mma.sync.aligned.m16n8k16.row.col.f32.f16.f16.f32 " \
                 "{%0,%1,%2,%3},{%4,%5,%6,%7},{%8,%9},{%0,%1,%2,%3};" \
                 : "+f"((D)[0]), "+f"((D)[1]), "+f"((D)[2]), "+f"((D)[3]) \
                 : "r"((A)[0]), "r"((A)[1]), "r"((A)[2]), "r"((A)[3]), "r"(B0), "r"(B1))

// ------------------------------- MMA GEMM ----------------------------------
// C[M,N] = alpha*(A @ Bmat^T)(+bias). A:[M,K] fp16 (ld=K), Bmat:[N,K] fp16 (ld=K).
// Block 128x256, 8 warps (2x4), warp tile 64x64, K-chunk 32, 3-stage cp.async.
#define BMm 128
#define BNm 256
#define BKm 32
#define LDSm 40                         // padded row length in halves (80B)
#define OPA (128 * LDSm * 2)            // 10240 B
#define OPBB (256 * LDSm * 2)           // 20480 B
#define STGB (OPA + OPBB)               // 30720 B
#define NSTAGE 3
#define SMEM_BYTES (NSTAGE * STGB)      // 92160

template<int EPI, bool BIAS>   // EPI 0: fp32 out ; EPI 1: fp16 out (+bias)
__global__ __launch_bounds__(256, 1)
void mma_gemm(const __half* __restrict__ A, const __half* __restrict__ B,
              const float* __restrict__ bias,
              float* __restrict__ Cf, __half* __restrict__ Ch,
              int K, int ldc,
              long long sA, long long sB, long long sC, long long sBias, float alpha)
{
    extern __shared__ char smem[];
    const uint32_t sbase = smem_u32(smem);
    const int tid  = threadIdx.x;
    const int wid  = tid >> 5;
    const int lane = tid & 31;
    const int wy = wid >> 2;            // 0..1  (m, 64 rows each)
    const int wx = wid & 3;             // 0..3  (n, 64 cols each)
    const int m0 = blockIdx.y * BMm;
    const int n0 = blockIdx.x * BNm;
    A += (long long)blockIdx.z * sA;
    B += (long long)blockIdx.z * sB;
    if (BIAS) bias += (long long)blockIdx.z * sBias;

    float acc[4][8][4];
#pragma unroll
    for (int i = 0; i < 4; i++)
#pragma unroll
        for (int j = 0; j < 8; j++)
#pragma unroll
            for (int q = 0; q < 4; q++) acc[i][j][q] = 0.0f;

    const int nch = K / BKm;

    auto load_stage = [&](int s, int k0) {
        uint32_t sb = sbase + s * STGB;
        // A: 128 rows x 32 halves = 512 x 16B chunks
#pragma unroll
        for (int t = 0; t < 2; t++) {
            int idx = tid + 256 * t;
            int r = idx >> 2, c = idx & 3;
            CP16(sb + (uint32_t)(r * LDSm + c * 8) * 2,
                 A + (long long)(m0 + r) * K + k0 + c * 8);
        }
        // B: 256 rows x 32 halves = 1024 x 16B chunks
#pragma unroll
        for (int t = 0; t < 4; t++) {
            int idx = tid + 256 * t;
            int r = idx >> 2, c = idx & 3;
            CP16(sb + OPA + (uint32_t)(r * LDSm + c * 8) * 2,
                 B + (long long)(n0 + r) * K + k0 + c * 8);
        }
    };

    load_stage(0, 0);       CP_COMMIT();
    load_stage(1, BKm);     CP_COMMIT();

    // ldmatrix lane address components
    const int arow = (lane & 7) + ((lane >> 3) & 1) * 8;   // 0..15
    const int acol = (lane >> 4) * 8;                      // 0 / 8
    const int brow = (lane & 7) + (lane >> 4) * 8;
    const int bcol = ((lane >> 3) & 1) * 8;

    for (int c = 0; c < nch; c++) {
        CP_WAIT1();
        __syncthreads();
        if (c + 2 < nch) load_stage((c + 2) % NSTAGE, (c + 2) * BKm);
        CP_COMMIT();

        const uint32_t sb = sbase + (c % NSTAGE) * STGB;
#pragma unroll
        for (int ks = 0; ks < 2; ks++) {
            uint32_t af[4][4];
#pragma unroll
            for (int i = 0; i < 4; i++) {
                uint32_t aoff = (uint32_t)((64 * wy + 16 * i + arow) * LDSm
                                           + ks * 16 + acol) * 2;
                LDSM4(af[i][0], af[i][1], af[i][2], af[i][3], sb + aoff);
            }
            uint32_t bf[8][2];
#pragma unroll
            for (int jp = 0; jp < 4; jp++) {
                uint32_t boff = (uint32_t)((64 * wx + 16 * jp + brow) * LDSm
                                           + ks * 16 + bcol) * 2;
                LDSM4(bf[2*jp][0], bf[2*jp][1], bf[2*jp+1][0], bf[2*jp+1][1],
                      sb + OPA + boff);
            }
#pragma unroll
            for (int i = 0; i < 4; i++)
#pragma unroll
                for (int j = 0; j < 8; j++)
                    MMAH(acc[i][j], af[i], bf[j][0], bf[j][1]);
        }
        __syncthreads();
    }

    // ------------------------------ epilogue --------------------------------
    const int g  = lane >> 2;
    const int t4 = lane & 3;
    const long long cb = (long long)blockIdx.z * sC;
#pragma unroll
    for (int i = 0; i < 4; i++) {
#pragma unroll
        for (int j = 0; j < 8; j++) {
            int mrow = m0 + 64 * wy + 16 * i + g;
            int ncol = n0 + 64 * wx + 8 * j + 2 * t4;
            float v00 = acc[i][j][0] * alpha, v01 = acc[i][j][1] * alpha;
            float v10 = acc[i][j][2] * alpha, v11 = acc[i][j][3] * alpha;
            long long o0 = cb + (long long)mrow * ldc + ncol;
            long long o1 = cb + (long long)(mrow + 8) * ldc + ncol;
            if (EPI == 0) {
                *(float2*)(Cf + o0) = make_float2(v00, v01);
                *(float2*)(Cf + o1) = make_float2(v10, v11);
            } else {
                if (BIAS) {
                    float b0 = bias[ncol], b1 = bias[ncol + 1];
                    v00 += b0; v01 += b1; v10 += b0; v11 += b1;
                }
                *(__half2*)(Ch + o0) = __floats2half2_rn(v00, v01);
                *(__half2*)(Ch + o1) = __floats2half2_rn(v10, v11);
            }
        }
    }
}

// --------------------------- aux kernels ------------------------------------
// fp32 -> fp16, 4 elts/thread
__global__ void cvt_x(const float* __restrict__ in, __half* __restrict__ out)
{
    long long i = ((long long)blockIdx.x * blockDim.x + threadIdx.x) * 4;
    float4 v = *(const float4*)(in + i);
    __half2 h0 = __floats2half2_rn(v.x, v.y);
    __half2 h1 = __floats2half2_rn(v.z, v.w);
    *(__half2*)(out + i)     = h0;
    *(__half2*)(out + i + 2) = h1;
}

__global__ void copy_bias(const float* __restrict__ b0, const float* __restrict__ b1,
                          const float* __restrict__ b2, float* __restrict__ dst)
{
    int z = blockIdx.x;
    const float* s = (z == 0) ? b0 : (z == 1) ? b1 : b2;
    dst[z * Dd + threadIdx.x] = s[threadIdx.x];
}

// Wt[n,k] = W[k,n] fp16 ; z selects which W
__global__ void transW(const float* __restrict__ W0, const float* __restrict__ W1,
                       const float* __restrict__ W2, __half* __restrict__ out)
{
    __shared__ float t[32][33];
    const float* W = (blockIdx.z == 0) ? W0 : (blockIdx.z == 1) ? W1 : W2;
    __half* o = out + (size_t)blockIdx.z * Dd * Dd;
    int bx = blockIdx.x * 32, by = blockIdx.y * 32;
    int tx = threadIdx.x, ty = threadIdx.y;
#pragma unroll
    for (int r = 0; r < 4; r++)
        t[ty + 8 * r][tx] = W[(long long)(by + ty + 8 * r) * Dd + bx + tx];
    __syncthreads();
#pragma unroll
    for (int r = 0; r < 4; r++)
        o[(long long)(bx + ty + 8 * r) * Dd + by + tx] = __float2half_rn(t[tx][ty + 8 * r]);
}

// per-batch fp16 transpose: in [2048,1024] -> out [1024,2048]
__global__ void transV(const __half* __restrict__ in, __half* __restrict__ out)
{
    __shared__ __half t[32][34];
    long long zi = (long long)blockIdx.z * Nn * Dd;
    int bx = blockIdx.x * 32, by = blockIdx.y * 32;
    int tx = threadIdx.x, ty = threadIdx.y;
#pragma unroll
    for (int r = 0; r < 4; r++)
        t[ty + 8 * r][tx] = in[zi + (long long)(by + ty + 8 * r) * Dd + bx + tx];
    __syncthreads();
#pragma unroll
    for (int r = 0; r < 4; r++)
        out[zi + (long long)(bx + ty + 8 * r) * Nn + by + tx] = t[tx][ty + 8 * r];
}

// in-place row softmax + fp16 emission
__global__ void softmax_split(float* __restrict__ W, __half* __restrict__ wh)
{
    long long row = blockIdx.x;
    float* p = W + row * (long long)Nn;
    __half* ph = wh + row * (long long)Nn;
    __shared__ float red[256];
    int tid = threadIdx.x;

    float mx = -INFINITY;
#pragma unroll
    for (int i = 0; i < 8; i++) mx = fmaxf(mx, p[tid + i * 256]);
    red[tid] = mx; __syncthreads();
#pragma unroll
    for (int s = 128; s > 0; s >>= 1) {
        if (tid < s) red[tid] = fmaxf(red[tid], red[tid + s]);
        __syncthreads();
    }
    mx = red[0]; __syncthreads();

    float e[8], sum = 0.0f;
#pragma unroll
    for (int i = 0; i < 8; i++) { e[i] = expf(p[tid + i * 256] - mx); sum += e[i]; }
    red[tid] = sum; __syncthreads();
#pragma unroll
    for (int s = 128; s > 0; s >>= 1) {
        if (tid < s) red[tid] += red[tid + s];
        __syncthreads();
    }
    float inv = 1.0f / red[0];
#pragma unroll
    for (int i = 0; i < 8; i++) {
        int c = tid + i * 256;
        float v = e[i] * inv;
        p[c] = v;
        ph[c] = __float2half_rn(v);
    }
}

// residual + layernorm + concat(x, ln)
__global__ void ln_concat(const float* __restrict__ x, const float* __restrict__ att,
                          const float* __restrict__ gamma, const float* __restrict__ beta,
                          float* __restrict__ out)
{
    long long row = blockIdx.x;
    const float* xr = x + row * Dd;
    const float* ar = att + row * Dd;
    float* o = out + row * (2 * Dd);
    __shared__ float red[256];
    int tid = threadIdx.x;

    float h[4], s = 0.0f;
#pragma unroll
    for (int i = 0; i < 4; i++) { int c = tid + i * 256; h[i] = xr[c] + ar[c]; s += h[i]; }
    red[tid] = s; __syncthreads();
#pragma unroll
    for (int st = 128; st > 0; st >>= 1) {
        if (tid < st) red[tid] += red[tid + st];
        __syncthreads();
    }
    float mu = red[0] * (1.0f / Dd); __syncthreads();

    float v = 0.0f;
#pragma unroll
    for (int i = 0; i < 4; i++) { float d = h[i] - mu; v += d * d; }
    red[tid] = v; __syncthreads();
#pragma unroll
    for (int st = 128; st > 0; st >>= 1) {
        if (tid < st) red[tid] += red[tid + st];
        __syncthreads();
    }
    float rstd = rsqrtf(red[0] * (1.0f / Dd) + 1e-5f);
#pragma unroll
    for (int i = 0; i < 4; i++) {
        int c = tid + i * 256;
        o[c]      = xr[c];
        o[Dd + c] = (h[i] - mu) * rstd * gamma[c] + beta[c];
    }
}

// ------------------------------- launcher -----------------------------------
extern "C" void kernel_launch(void* const* d_in, const int* in_sizes, int n_in,
                              void* d_out, int out_size)
{
    const float* x     = (const float*)d_in[0];
    const float* Wk    = (const float*)d_in[1];
    const float* bk    = (const float*)d_in[2];
    const float* Wq    = (const float*)d_in[3];
    const float* bq    = (const float*)d_in[4];
    const float* Wv    = (const float*)d_in[5];
    const float* bv    = (const float*)d_in[6];
    const float* gamma = (const float*)d_in[7];
    const float* beta  = (const float*)d_in[8];

    float* out = (float*)d_out;
    float* att = out + (long long)MT * 2 * Dd;
    float* wgt = att + (long long)MT * Dd;

    __half *x16, *W16, *QKV, *Vt, *w16;
    float* bqkv;
    cudaGetSymbolAddress((void**)&x16, g_x16);
    cudaGetSymbolAddress((void**)&W16, g_W16);
    cudaGetSymbolAddress((void**)&bqkv, g_b);
    cudaGetSymbolAddress((void**)&QKV, g_QKV);
    cudaGetSymbolAddress((void**)&Vt,  g_Vt);
    cudaGetSymbolAddress((void**)&w16, g_w16);

    cudaFuncSetAttribute(mma_gemm<0, false>, cudaFuncAttributeMaxDynamicSharedMemorySize, SMEM_BYTES);
    cudaFuncSetAttribute(mma_gemm<1, true>,  cudaFuncAttributeMaxDynamicSharedMemorySize, SMEM_BYTES);

    // 1) precision conversions
    cvt_x<<<MT * Dd / 4096, 1024>>>(x, x16);
    copy_bias<<<3, Dd>>>(bq, bk, bv, bqkv);
    {
        dim3 g(Dd / 32, Dd / 32, 3), b(32, 8);
        transW<<<g, b>>>(Wq, Wk, Wv, W16);
    }

    // 2) fused QKV projection: z in {Q,K,V}
    {
        dim3 g(Dd / BNm, MT / BMm, 3), b(256);
        mma_gemm<1, true><<<g, b, SMEM_BYTES>>>(x16, W16, bqkv, nullptr, QKV,
                                                Dd, Dd,
                                                0, (long long)Dd * Dd, (long long)MT * Dd,
                                                Dd, 1.0f);
    }

    // 3) V transpose per batch: [n,d] -> [d,n]
    {
        dim3 g(Dd / 32, Nn / 32, Bb), b(32, 8);
        transV<<<g, b>>>(QKV + (size_t)2 * MT * Dd, Vt);
    }

    // 4) scores = Q @ K^T / 32 -> wgt (fp32)
    {
        dim3 g(Nn / BNm, Nn / BMm, Bb), b(256);
        mma_gemm<0, false><<<g, b, SMEM_BYTES>>>(QKV, QKV + (size_t)MT * Dd, nullptr,
                                                 wgt, nullptr,
                                                 Dd, Nn,
                                                 (long long)Nn * Dd, (long long)Nn * Dd,
                                                 (long long)Nn * Nn, 0, 1.0f / 32.0f);
    }

    // 5) softmax rows in place + fp16 copy
    softmax_split<<<Bb * Nn, 256>>>(wgt, w16);

    // 6) att = weight @ V^T^T -> att (fp32)
    {
        dim3 g(Dd / BNm, Nn / BMm, Bb), b(256);
        mma_gemm<0, false><<<g, b, SMEM_BYTES>>>(w16, Vt, nullptr, att, nullptr,
                                                 Nn, Dd,
                                                 (long long)Nn * Nn, (long long)Nn * Dd,
                                                 (long long)Nn * Dd, 0, 1.0f);
    }

    // 7) out = concat(x, LN(x + att))
    ln_concat<<<Bb * Nn, 256>>>(x, att, gamma, beta, out);
}

// round 5
// speedup vs baseline: 5.6243x; 1.1442x over previous
#include <cuda_runtime.h>
#include <cuda_fp16.h>
#include <math.h>
#include <stdint.h>

// ---------------------------------------------------------------------------
// attention_83932250898666 : B=4, N=2048, D=1024
// d_out layout (float32):
//   [0, 16777216)        out   = concat(x, LN(x+att))   [B,N,2D]
//   [16777216, 25165824) att_score                      [B,N,D]
//   [25165824, 41943040) weight = softmax(QK^T/32)      [B,N,N]
// GEMMs: single-pass fp16 mma.sync (HMMA), fp32 accumulate.
// Round 5: BK=64, 1 sync/chunk, register double-buffered fragments.
// ---------------------------------------------------------------------------

#define Bb 4
#define Nn 2048
#define Dd 1024
#define MT (Bb*Nn)   // 8192

// ------------------------- device scratch (no allocs) ----------------------
__device__ __half g_x16[(size_t)MT * Dd];
__device__ __half g_W16[(size_t)3 * Dd * Dd];      // [z][n][k] transposed weights
__device__ float  g_b[3 * Dd];                     // biases q,k,v
__device__ __half g_QKV[(size_t)3 * MT * Dd];      // Q | K | V
__device__ __half g_Vt[(size_t)MT * Dd];           // per-batch V^T [b][d][n]
__device__ __half g_w16[(size_t)Bb * Nn * Nn];     // softmax weights fp16

// ------------------------------ PTX helpers --------------------------------
__device__ __forceinline__ uint32_t smem_u32(const void* p) {
    uint32_t a;
    asm("{ .reg .u64 t; cvta.to.shared.u64 t, %1; cvt.u32.u64 %0, t; }" : "=r"(a) : "l"(p));
    return a;
}

#define CP16(dst, src) \
    asm volatile("cp.async.cg.shared.global [%0], [%1], 16;" :: "r"(dst), "l"(src))
#define CP_COMMIT() asm volatile("cp.async.commit_group;" ::: "memory")
#define CP_WAIT1()  asm volatile("cp.async.wait_group 1;" ::: "memory")

#define LDSM4(R0, R1, R2, R3, A) \
    asm volatile("ldmatrix.sync.aligned.m8n8.x4.shared.b16 {%0,%1,%2,%3}, [%4];" \
                 : "=r"(R0), "=r"(R1), "=r"(R2), "=r"(R3) : "r"(A))

#define MMAH(D, A, B0, B1) \
    asm volatile("mma.sync.aligned.m16n8k16.row.col.f32.f16.f16.f32 " \
                 "{%0,%1,%2,%3},{%4,%5,%6,%7},{%8,%9},{%0,%1,%2,%3};" \
                 : "+f"((D)[0]), "+f"((D)[1]), "+f"((D)[2]), "+f"((D)[3]) \
                 : "r"((A)[0]), "r"((A)[1]), "r"((A)[2]), "r"((A)[3]), "r"(B0), "r"(B1))

// ------------------------------- MMA GEMM ----------------------------------
// C[M,N] = alpha*(A @ Bmat^T)(+bias). A:[M,K] fp16 (ld=K), Bmat:[N,K] fp16 (ld=K).
// Block 128x256, 8 warps (2x4), warp tile 64x64, K-chunk 64, 3-stage cp.async.
#define BMm 128
#define BNm 256
#define BKm 64
#define LDSm 72                          // padded row length in halves (144B)
#define OPA (128 * LDSm * 2)             // 18432 B
#define OPBB (256 * LDSm * 2)            // 36864 B
#define STGB (OPA + OPBB)                // 55296 B
#define NSTAGE 3
#define SMEM_BYTES (NSTAGE * STGB)       // 165888

template<int EPI, bool BIAS>   // EPI 0: fp32 out ; EPI 1: fp16 out (+bias)
__global__ __launch_bounds__(256, 1)
void mma_gemm(const __half* __restrict__ A, const __half* __restrict__ B,
              const float* __restrict__ bias,
              float* __restrict__ Cf, __half* __restrict__ Ch,
              int K, int ldc,
              long long sA, long long sB, long long sC, long long sBias, float alpha)
{
    extern __shared__ char smem[];
    const uint32_t sbase = smem_u32(smem);
    const int tid  = threadIdx.x;
    const int wid  = tid >> 5;
    const int lane = tid & 31;
    const int wy = wid >> 2;            // 0..1  (m, 64 rows each)
    const int wx = wid & 3;             // 0..3  (n, 64 cols each)
    const int m0 = blockIdx.y * BMm;
    const int n0 = blockIdx.x * BNm;
    A += (long long)blockIdx.z * sA;
    B += (long long)blockIdx.z * sB;
    if (BIAS) bias += (long long)blockIdx.z * sBias;

    float acc[4][8][4];
#pragma unroll
    for (int i = 0; i < 4; i++)
#pragma unroll
        for (int j = 0; j < 8; j++)
#pragma unroll
            for (int q = 0; q < 4; q++) acc[i][j][q] = 0.0f;

    const int nch = K / BKm;

    auto load_stage = [&](int s, int k0) {
        uint32_t sb = sbase + s * STGB;
        // A: 128 rows x 64 halves = 1024 x 16B chunks (4/thread)
#pragma unroll
        for (int t = 0; t < 4; t++) {
            int idx = tid + 256 * t;
            int r = idx >> 3, c = idx & 7;
            CP16(sb + (uint32_t)(r * LDSm + c * 8) * 2,
                 A + (long long)(m0 + r) * K + k0 + c * 8);
        }
        // B: 256 rows x 64 halves = 2048 x 16B chunks (8/thread)
#pragma unroll
        for (int t = 0; t < 8; t++) {
            int idx = tid + 256 * t;
            int r = idx >> 3, c = idx & 7;
            CP16(sb + OPA + (uint32_t)(r * LDSm + c * 8) * 2,
                 B + (long long)(n0 + r) * K + k0 + c * 8);
        }
    };

    load_stage(0, 0);       CP_COMMIT();
    load_stage(1, BKm);     CP_COMMIT();

    // ldmatrix lane address components
    const int arow = (lane & 7) + ((lane >> 3) & 1) * 8;   // 0..15
    const int acol = (lane >> 4) * 8;                      // 0 / 8
    const int brow = (lane & 7) + (lane >> 4) * 8;
    const int bcol = ((lane >> 3) & 1) * 8;

    uint32_t af[2][4][4], bf[2][8][2];

    auto ldfrag = [&](int buf, uint32_t sb, int ks) {
#pragma unroll
        for (int i = 0; i < 4; i++) {
            uint32_t aoff = (uint32_t)((64 * wy + 16 * i + arow) * LDSm
                                       + ks * 16 + acol) * 2;
            LDSM4(af[buf][i][0], af[buf][i][1], af[buf][i][2], af[buf][i][3], sb + aoff);
        }
#pragma unroll
        for (int jp = 0; jp < 4; jp++) {
            uint32_t boff = (uint32_t)((64 * wx + 16 * jp + brow) * LDSm
                                       + ks * 16 + bcol) * 2;
            LDSM4(bf[buf][2*jp][0], bf[buf][2*jp][1], bf[buf][2*jp+1][0], bf[buf][2*jp+1][1],
                  sb + OPA + boff);
        }
    };

    for (int c = 0; c < nch; c++) {
        CP_WAIT1();
        __syncthreads();
        if (c + 2 < nch) load_stage((c + 2) % NSTAGE, (c + 2) * BKm);
        CP_COMMIT();

        const uint32_t sb = sbase + (c % NSTAGE) * STGB;
        ldfrag(0, sb, 0);
#pragma unroll
        for (int ks = 0; ks < 4; ks++) {
            if (ks < 3) ldfrag((ks + 1) & 1, sb, ks + 1);
            const int cur = ks & 1;
#pragma unroll
            for (int i = 0; i < 4; i++)
#pragma unroll
                for (int j = 0; j < 8; j++)
                    MMAH(acc[i][j], af[cur][i], bf[cur][j][0], bf[cur][j][1]);
        }
    }

    // ------------------------------ epilogue --------------------------------
    const int g  = lane >> 2;
    const int t4 = lane & 3;
    const long long cb = (long long)blockIdx.z * sC;
#pragma unroll
    for (int i = 0; i < 4; i++) {
#pragma unroll
        for (int j = 0; j < 8; j++) {
            int mrow = m0 + 64 * wy + 16 * i + g;
            int ncol = n0 + 64 * wx + 8 * j + 2 * t4;
            float v00 = acc[i][j][0] * alpha, v01 = acc[i][j][1] * alpha;
            float v10 = acc[i][j][2] * alpha, v11 = acc[i][j][3] * alpha;
            long long o0 = cb + (long long)mrow * ldc + ncol;
            long long o1 = cb + (long long)(mrow + 8) * ldc + ncol;
            if (EPI == 0) {
                *(float2*)(Cf + o0) = make_float2(v00, v01);
                *(float2*)(Cf + o1) = make_float2(v10, v11);
            } else {
                if (BIAS) {
                    float b0 = bias[ncol], b1 = bias[ncol + 1];
                    v00 += b0; v01 += b1; v10 += b0; v11 += b1;
                }
                *(__half2*)(Ch + o0) = __floats2half2_rn(v00, v01);
                *(__half2*)(Ch + o1) = __floats2half2_rn(v10, v11);
            }
        }
    }
}

// --------------------------- aux kernels ------------------------------------
// fp32 -> fp16, 4 elts/thread
__global__ void cvt_x(const float* __restrict__ in, __half* __restrict__ out)
{
    long long i = ((long long)blockIdx.x * blockDim.x + threadIdx.x) * 4;
    float4 v = *(const float4*)(in + i);
    *(__half2*)(out + i)     = __floats2half2_rn(v.x, v.y);
    *(__half2*)(out + i + 2) = __floats2half2_rn(v.z, v.w);
}

__global__ void copy_bias(const float* __restrict__ b0, const float* __restrict__ b1,
                          const float* __restrict__ b2, float* __restrict__ dst)
{
    int z = blockIdx.x;
    const float* s = (z == 0) ? b0 : (z == 1) ? b1 : b2;
    dst[z * Dd + threadIdx.x] = s[threadIdx.x];
}

// Wt[n,k] = W[k,n] fp16 ; z selects which W
__global__ void transW(const float* __restrict__ W0, const float* __restrict__ W1,
                       const float* __restrict__ W2, __half* __restrict__ out)
{
    __shared__ float t[32][33];
    const float* W = (blockIdx.z == 0) ? W0 : (blockIdx.z == 1) ? W1 : W2;
    __half* o = out + (size_t)blockIdx.z * Dd * Dd;
    int bx = blockIdx.x * 32, by = blockIdx.y * 32;
    int tx = threadIdx.x, ty = threadIdx.y;
#pragma unroll
    for (int r = 0; r < 4; r++)
        t[ty + 8 * r][tx] = W[(long long)(by + ty + 8 * r) * Dd + bx + tx];
    __syncthreads();
#pragma unroll
    for (int r = 0; r < 4; r++)
        o[(long long)(bx + ty + 8 * r) * Dd + by + tx] = __float2half_rn(t[tx][ty + 8 * r]);
}

// per-batch fp16 transpose: in [2048,1024] -> out [1024,2048]
__global__ void transV(const __half* __restrict__ in, __half* __restrict__ out)
{
    __shared__ __half t[32][34];
    long long zi = (long long)blockIdx.z * Nn * Dd;
    int bx = blockIdx.x * 32, by = blockIdx.y * 32;
    int tx = threadIdx.x, ty = threadIdx.y;
#pragma unroll
    for (int r = 0; r < 4; r++)
        t[ty + 8 * r][tx] = in[zi + (long long)(by + ty + 8 * r) * Dd + bx + tx];
    __syncthreads();
#pragma unroll
    for (int r = 0; r < 4; r++)
        out[zi + (long long)(bx + ty + 8 * r) * Nn + by + tx] = t[tx][ty + 8 * r];
}

// in-place row softmax + fp16 emission
__global__ void softmax_split(float* __restrict__ W, __half* __restrict__ wh)
{
    long long row = blockIdx.x;
    float* p = W + row * (long long)Nn;
    __half* ph = wh + row * (long long)Nn;
    __shared__ float red[256];
    int tid = threadIdx.x;

    float mx = -INFINITY;
#pragma unroll
    for (int i = 0; i < 8; i++) mx = fmaxf(mx, p[tid + i * 256]);
    red[tid] = mx; __syncthreads();
#pragma unroll
    for (int s = 128; s > 0; s >>= 1) {
        if (tid < s) red[tid] = fmaxf(red[tid], red[tid + s]);
        __syncthreads();
    }
    mx = red[0]; __syncthreads();

    float e[8], sum = 0.0f;
#pragma unroll
    for (int i = 0; i < 8; i++) { e[i] = expf(p[tid + i * 256] - mx); sum += e[i]; }
    red[tid] = sum; __syncthreads();
#pragma unroll
    for (int s = 128; s > 0; s >>= 1) {
        if (tid < s) red[tid] += red[tid + s];
        __syncthreads();
    }
    float inv = 1.0f / red[0];
#pragma unroll
    for (int i = 0; i < 8; i++) {
        int c = tid + i * 256;
        float v = e[i] * inv;
        p[c] = v;
        ph[c] = __float2half_rn(v);
    }
}

// residual + layernorm + concat(x, ln)
__global__ void ln_concat(const float* __restrict__ x, const float* __restrict__ att,
                          const float* __restrict__ gamma, const float* __restrict__ beta,
                          float* __restrict__ out)
{
    long long row = blockIdx.x;
    const float* xr = x + row * Dd;
    const float* ar = att + row * Dd;
    float* o = out + row * (2 * Dd);
    __shared__ float red[256];
    int tid = threadIdx.x;

    float h[4], s = 0.0f;
#pragma unroll
    for (int i = 0; i < 4; i++) { int c = tid + i * 256; h[i] = xr[c] + ar[c]; s += h[i]; }
    red[tid] = s; __syncthreads();
#pragma unroll
    for (int st = 128; st > 0; st >>= 1) {
        if (tid < st) red[tid] += red[tid + st];
        __syncthreads();
    }
    float mu = red[0] * (1.0f / Dd); __syncthreads();

    float v = 0.0f;
#pragma unroll
    for (int i = 0; i < 4; i++) { float d = h[i] - mu; v += d * d; }
    red[tid] = v; __syncthreads();
#pragma unroll
    for (int st = 128; st > 0; st >>= 1) {
        if (tid < st) red[tid] += red[tid + st];
        __syncthreads();
    }
    float rstd = rsqrtf(red[0] * (1.0f / Dd) + 1e-5f);
#pragma unroll
    for (int i = 0; i < 4; i++) {
        int c = tid + i * 256;
        o[c]      = xr[c];
        o[Dd + c] = (h[i] - mu) * rstd * gamma[c] + beta[c];
    }
}

// ------------------------------- launcher -----------------------------------
extern "C" void kernel_launch(void* const* d_in, const int* in_sizes, int n_in,
                              void* d_out, int out_size)
{
    const float* x     = (const float*)d_in[0];
    const float* Wk    = (const float*)d_in[1];
    const float* bk    = (const float*)d_in[2];
    const float* Wq    = (const float*)d_in[3];
    const float* bq    = (const float*)d_in[4];
    const float* Wv    = (const float*)d_in[5];
    const float* bv    = (const float*)d_in[6];
    const float* gamma = (const float*)d_in[7];
    const float* beta  = (const float*)d_in[8];

    float* out = (float*)d_out;
    float* att = out + (long long)MT * 2 * Dd;
    float* wgt = att + (long long)MT * Dd;

    __half *x16, *W16, *QKV, *Vt, *w16;
    float* bqkv;
    cudaGetSymbolAddress((void**)&x16, g_x16);
    cudaGetSymbolAddress((void**)&W16, g_W16);
    cudaGetSymbolAddress((void**)&bqkv, g_b);
    cudaGetSymbolAddress((void**)&QKV, g_QKV);
    cudaGetSymbolAddress((void**)&Vt,  g_Vt);
    cudaGetSymbolAddress((void**)&w16, g_w16);

    cudaFuncSetAttribute(mma_gemm<0, false>, cudaFuncAttributeMaxDynamicSharedMemorySize, SMEM_BYTES);
    cudaFuncSetAttribute(mma_gemm<1, true>,  cudaFuncAttributeMaxDynamicSharedMemorySize, SMEM_BYTES);

    // 1) precision conversions
    cvt_x<<<MT * Dd / 4096, 1024>>>(x, x16);
    copy_bias<<<3, Dd>>>(bq, bk, bv, bqkv);
    {
        dim3 g(Dd / 32, Dd / 32, 3), b(32, 8);
        transW<<<g, b>>>(Wq, Wk, Wv, W16);
    }

    // 2) fused QKV projection: z in {Q,K,V}
    {
        dim3 g(Dd / BNm, MT / BMm, 3), b(256);
        mma_gemm<1, true><<<g, b, SMEM_BYTES>>>(x16, W16, bqkv, nullptr, QKV,
                                                Dd, Dd,
                                                0, (long long)Dd * Dd, (long long)MT * Dd,
                                                Dd, 1.0f);
    }

    // 3) V transpose per batch: [n,d] -> [d,n]
    {
        dim3 g(Dd / 32, Nn / 32, Bb), b(32, 8);
        transV<<<g, b>>>(QKV + (size_t)2 * MT * Dd, Vt);
    }

    // 4) scores = Q @ K^T / 32 -> wgt (fp32)
    {
        dim3 g(Nn / BNm, Nn / BMm, Bb), b(256);
        mma_gemm<0, false><<<g, b, SMEM_BYTES>>>(QKV, QKV + (size_t)MT * Dd, nullptr,
                                                 wgt, nullptr,
                                                 Dd, Nn,
                                                 (long long)Nn * Dd, (long long)Nn * Dd,
                                                 (long long)Nn * Nn, 0, 1.0f / 32.0f);
    }

    // 5) softmax rows in place + fp16 copy
    softmax_split<<<Bb * Nn, 256>>>(wgt, w16);

    // 6) att = weight @ V -> att (fp32)
    {
        dim3 g(Dd / BNm, Nn / BMm, Bb), b(256);
        mma_gemm<0, false><<<g, b, SMEM_BYTES>>>(w16, Vt, nullptr, att, nullptr,
                                                 Nn, Dd,
                                                 (long long)Nn * Nn, (long long)Nn * Dd,
                                                 (long long)Nn * Dd, 0, 1.0f);
    }

    // 7) out = concat(x, LN(x + att))
    ln_concat<<<Bb * Nn, 256>>>(x, att, gamma, beta, out);
}

// round 6
// speedup vs baseline: 6.2224x; 1.1063x over previous
#include <cuda_runtime.h>
#include <cuda_fp16.h>
#include <math.h>
#include <stdint.h>

// ---------------------------------------------------------------------------
// attention_83932250898666 : B=4, N=2048, D=1024
// d_out layout (float32):
//   [0, 16777216)        out   = concat(x, LN(x+att))   [B,N,2D]
//   [16777216, 25165824) att_score                      [B,N,D]
//   [25165824, 41943040) weight = softmax(QK^T/32)      [B,N,N]
// GEMMs: single-pass fp16 mma.sync (HMMA), fp32 accumulate.
// Round 6: block 128x128, warp 32x64, 2 CTAs/SM (16 warps/SM).
// ---------------------------------------------------------------------------

#define Bb 4
#define Nn 2048
#define Dd 1024
#define MT (Bb*Nn)   // 8192

// ------------------------- device scratch (no allocs) ----------------------
__device__ __half g_x16[(size_t)MT * Dd];
__device__ __half g_W16[(size_t)3 * Dd * Dd];      // [z][n][k] transposed weights
__device__ float  g_b[3 * Dd];                     // biases q,k,v
__device__ __half g_QKV[(size_t)3 * MT * Dd];      // Q | K | V
__device__ __half g_Vt[(size_t)MT * Dd];           // per-batch V^T [b][d][n]
__device__ __half g_w16[(size_t)Bb * Nn * Nn];     // softmax weights fp16

// ------------------------------ PTX helpers --------------------------------
__device__ __forceinline__ uint32_t smem_u32(const void* p) {
    uint32_t a;
    asm("{ .reg .u64 t; cvta.to.shared.u64 t, %1; cvt.u32.u64 %0, t; }" : "=r"(a) : "l"(p));
    return a;
}

#define CP16(dst, src) \
    asm volatile("cp.async.cg.shared.global [%0], [%1], 16;" :: "r"(dst), "l"(src))
#define CP_COMMIT() asm volatile("cp.async.commit_group;" ::: "memory")
#define CP_WAIT1()  asm volatile("cp.async.wait_group 1;" ::: "memory")

#define LDSM4(R0, R1, R2, R3, A) \
    asm volatile("ldmatrix.sync.aligned.m8n8.x4.shared.b16 {%0,%1,%2,%3}, [%4];" \
                 : "=r"(R0), "=r"(R1), "=r"(R2), "=r"(R3) : "r"(A))

#define MMAH(D, A0, A1, A2, A3, B0, B1) \
    asm volatile("mma.sync.aligned.m16n8k16.row.col.f32.f16.f16.f32 " \
                 "{%0,%1,%2,%3},{%4,%5,%6,%7},{%8,%9},{%0,%1,%2,%3};" \
                 : "+f"((D)[0]), "+f"((D)[1]), "+f"((D)[2]), "+f"((D)[3]) \
                 : "r"(A0), "r"(A1), "r"(A2), "r"(A3), "r"(B0), "r"(B1))

// ------------------------------- MMA GEMM ----------------------------------
// C[M,N] = alpha*(A @ Bmat^T)(+bias). A:[M,K] fp16 (ld=K), Bmat:[N,K] fp16 (ld=K).
// Block 128x128, 8 warps (4m x 2n), warp tile 32x64, K-chunk 64, 3-stage cp.async.
#define BMm 128
#define BNm 128
#define BKm 64
#define LDSm 72                          // padded row length in halves (144B)
#define OPA (128 * LDSm * 2)             // 18432 B
#define STGB (2 * OPA)                   // 36864 B
#define NSTAGE 3
#define SMEM_BYTES (NSTAGE * STGB)       // 110592

template<int EPI, bool BIAS>   // EPI 0: fp32 out ; EPI 1: fp16 out (+bias)
__global__ __launch_bounds__(256, 2)
void mma_gemm(const __half* __restrict__ A, const __half* __restrict__ B,
              const float* __restrict__ bias,
              float* __restrict__ Cf, __half* __restrict__ Ch,
              int K, int ldc,
              long long sA, long long sB, long long sC, long long sBias, float alpha)
{
    extern __shared__ char smem[];
    const uint32_t sbase = smem_u32(smem);
    const int tid  = threadIdx.x;
    const int wid  = tid >> 5;
    const int lane = tid & 31;
    const int wy = wid >> 1;            // 0..3  (m, 32 rows each)
    const int wx = wid & 1;             // 0..1  (n, 64 cols each)
    const int m0 = blockIdx.y * BMm;
    const int n0 = blockIdx.x * BNm;
    A += (long long)blockIdx.z * sA;
    B += (long long)blockIdx.z * sB;
    if (BIAS) bias += (long long)blockIdx.z * sBias;

    float acc[2][8][4];
#pragma unroll
    for (int i = 0; i < 2; i++)
#pragma unroll
        for (int j = 0; j < 8; j++)
#pragma unroll
            for (int q = 0; q < 4; q++) acc[i][j][q] = 0.0f;

    const int nch = K / BKm;

    auto load_stage = [&](int s, int k0) {
        uint32_t sb = sbase + s * STGB;
        // A: 128 rows x 64 halves = 1024 x 16B chunks (4/thread)
#pragma unroll
        for (int t = 0; t < 4; t++) {
            int idx = tid + 256 * t;
            int r = idx >> 3, c = idx & 7;
            CP16(sb + (uint32_t)(r * LDSm + c * 8) * 2,
                 A + (long long)(m0 + r) * K + k0 + c * 8);
        }
        // B: 128 rows x 64 halves = 1024 x 16B chunks (4/thread)
#pragma unroll
        for (int t = 0; t < 4; t++) {
            int idx = tid + 256 * t;
            int r = idx >> 3, c = idx & 7;
            CP16(sb + OPA + (uint32_t)(r * LDSm + c * 8) * 2,
                 B + (long long)(n0 + r) * K + k0 + c * 8);
        }
    };

    load_stage(0, 0);       CP_COMMIT();
    load_stage(1, BKm);     CP_COMMIT();

    // ldmatrix lane address components
    const int arow = (lane & 7) + ((lane >> 3) & 1) * 8;   // 0..15
    const int acol = (lane >> 4) * 8;                      // 0 / 8
    const int brow = (lane & 7) + (lane >> 4) * 8;
    const int bcol = ((lane >> 3) & 1) * 8;

    uint32_t af[2][2][4];      // A fragments, double buffered over ks
    uint32_t bf[8][2];         // B fragments, per-ks

    auto ldA = [&](int buf, uint32_t sb, int ks) {
#pragma unroll
        for (int i = 0; i < 2; i++) {
            uint32_t aoff = (uint32_t)((32 * wy + 16 * i + arow) * LDSm
                                       + ks * 16 + acol) * 2;
            LDSM4(af[buf][i][0], af[buf][i][1], af[buf][i][2], af[buf][i][3], sb + aoff);
        }
    };
    auto ldB = [&](uint32_t sb, int ks) {
#pragma unroll
        for (int jp = 0; jp < 4; jp++) {
            uint32_t boff = (uint32_t)((64 * wx + 16 * jp + brow) * LDSm
                                       + ks * 16 + bcol) * 2;
            LDSM4(bf[2*jp][0], bf[2*jp][1], bf[2*jp+1][0], bf[2*jp+1][1],
                  sb + OPA + boff);
        }
    };

    for (int c = 0; c < nch; c++) {
        CP_WAIT1();
        __syncthreads();
        if (c + 2 < nch) load_stage((c + 2) % NSTAGE, (c + 2) * BKm);
        CP_COMMIT();

        const uint32_t sb = sbase + (c % NSTAGE) * STGB;
        ldA(0, sb, 0);
#pragma unroll
        for (int ks = 0; ks < 4; ks++) {
            ldB(sb, ks);
            if (ks < 3) ldA((ks + 1) & 1, sb, ks + 1);
            const int cur = ks & 1;
#pragma unroll
            for (int i = 0; i < 2; i++)
#pragma unroll
                for (int j = 0; j < 8; j++)
                    MMAH(acc[i][j], af[cur][i][0], af[cur][i][1], af[cur][i][2],
                         af[cur][i][3], bf[j][0], bf[j][1]);
        }
    }

    // ------------------------------ epilogue --------------------------------
    const int g  = lane >> 2;
    const int t4 = lane & 3;
    const long long cb = (long long)blockIdx.z * sC;
#pragma unroll
    for (int i = 0; i < 2; i++) {
#pragma unroll
        for (int j = 0; j < 8; j++) {
            int mrow = m0 + 32 * wy + 16 * i + g;
            int ncol = n0 + 64 * wx + 8 * j + 2 * t4;
            float v00 = acc[i][j][0] * alpha, v01 = acc[i][j][1] * alpha;
            float v10 = acc[i][j][2] * alpha, v11 = acc[i][j][3] * alpha;
            long long o0 = cb + (long long)mrow * ldc + ncol;
            long long o1 = cb + (long long)(mrow + 8) * ldc + ncol;
            if (EPI == 0) {
                *(float2*)(Cf + o0) = make_float2(v00, v01);
                *(float2*)(Cf + o1) = make_float2(v10, v11);
            } else {
                if (BIAS) {
                    float b0 = bias[ncol], b1 = bias[ncol + 1];
                    v00 += b0; v01 += b1; v10 += b0; v11 += b1;
                }
                *(__half2*)(Ch + o0) = __floats2half2_rn(v00, v01);
                *(__half2*)(Ch + o1) = __floats2half2_rn(v10, v11);
            }
        }
    }
}

// --------------------------- aux kernels ------------------------------------
// fp32 -> fp16, 4 elts/thread
__global__ void cvt_x(const float* __restrict__ in, __half* __restrict__ out)
{
    long long i = ((long long)blockIdx.x * blockDim.x + threadIdx.x) * 4;
    float4 v = *(const float4*)(in + i);
    *(__half2*)(out + i)     = __floats2half2_rn(v.x, v.y);
    *(__half2*)(out + i + 2) = __floats2half2_rn(v.z, v.w);
}

__global__ void copy_bias(const float* __restrict__ b0, const float* __restrict__ b1,
                          const float* __restrict__ b2, float* __restrict__ dst)
{
    int z = blockIdx.x;
    const float* s = (z == 0) ? b0 : (z == 1) ? b1 : b2;
    dst[z * Dd + threadIdx.x] = s[threadIdx.x];
}

// Wt[n,k] = W[k,n] fp16 ; z selects which W
__global__ void transW(const float* __restrict__ W0, const float* __restrict__ W1,
                       const float* __restrict__ W2, __half* __restrict__ out)
{
    __shared__ float t[32][33];
    const float* W = (blockIdx.z == 0) ? W0 : (blockIdx.z == 1) ? W1 : W2;
    __half* o = out + (size_t)blockIdx.z * Dd * Dd;
    int bx = blockIdx.x * 32, by = blockIdx.y * 32;
    int tx = threadIdx.x, ty = threadIdx.y;
#pragma unroll
    for (int r = 0; r < 4; r++)
        t[ty + 8 * r][tx] = W[(long long)(by + ty + 8 * r) * Dd + bx + tx];
    __syncthreads();
#pragma unroll
    for (int r = 0; r < 4; r++)
        o[(long long)(bx + ty + 8 * r) * Dd + by + tx] = __float2half_rn(t[tx][ty + 8 * r]);
}

// per-batch fp16 transpose: in [2048,1024] -> out [1024,2048]
__global__ void transV(const __half* __restrict__ in, __half* __restrict__ out)
{
    __shared__ __half t[32][34];
    long long zi = (long long)blockIdx.z * Nn * Dd;
    int bx = blockIdx.x * 32, by = blockIdx.y * 32;
    int tx = threadIdx.x, ty = threadIdx.y;
#pragma unroll
    for (int r = 0; r < 4; r++)
        t[ty + 8 * r][tx] = in[zi + (long long)(by + ty + 8 * r) * Dd + bx + tx];
    __syncthreads();
#pragma unroll
    for (int r = 0; r < 4; r++)
        out[zi + (long long)(bx + ty + 8 * r) * Nn + by + tx] = t[tx][ty + 8 * r];
}

// in-place row softmax + fp16 emission
__global__ void softmax_split(float* __restrict__ W, __half* __restrict__ wh)
{
    long long row = blockIdx.x;
    float* p = W + row * (long long)Nn;
    __half* ph = wh + row * (long long)Nn;
    __shared__ float red[256];
    int tid = threadIdx.x;

    float mx = -INFINITY;
#pragma unroll
    for (int i = 0; i < 8; i++) mx = fmaxf(mx, p[tid + i * 256]);
    red[tid] = mx; __syncthreads();
#pragma unroll
    for (int s = 128; s > 0; s >>= 1) {
        if (tid < s) red[tid] = fmaxf(red[tid], red[tid + s]);
        __syncthreads();
    }
    mx = red[0]; __syncthreads();

    float e[8], sum = 0.0f;
#pragma unroll
    for (int i = 0; i < 8; i++) { e[i] = expf(p[tid + i * 256] - mx); sum += e[i]; }
    red[tid] = sum; __syncthreads();
#pragma unroll
    for (int s = 128; s > 0; s >>= 1) {
        if (tid < s) red[tid] += red[tid + s];
        __syncthreads();
    }
    float inv = 1.0f / red[0];
#pragma unroll
    for (int i = 0; i < 8; i++) {
        int c = tid + i * 256;
        float v = e[i] * inv;
        p[c] = v;
        ph[c] = __float2half_rn(v);
    }
}

// residual + layernorm + concat(x, ln)
__global__ void ln_concat(const float* __restrict__ x, const float* __restrict__ att,
                          const float* __restrict__ gamma, const float* __restrict__ beta,
                          float* __restrict__ out)
{
    long long row = blockIdx.x;
    const float* xr = x + row * Dd;
    const float* ar = att + row * Dd;
    float* o = out + row * (2 * Dd);
    __shared__ float red[256];
    int tid = threadIdx.x;

    float h[4], s = 0.0f;
#pragma unroll
    for (int i = 0; i < 4; i++) { int c = tid + i * 256; h[i] = xr[c] + ar[c]; s += h[i]; }
    red[tid] = s; __syncthreads();
#pragma unroll
    for (int st = 128; st > 0; st >>= 1) {
        if (tid < st) red[tid] += red[tid + st];
        __syncthreads();
    }
    float mu = red[0] * (1.0f / Dd); __syncthreads();

    float v = 0.0f;
#pragma unroll
    for (int i = 0; i < 4; i++) { float d = h[i] - mu; v += d * d; }
    red[tid] = v; __syncthreads();
#pragma unroll
    for (int st = 128; st > 0; st >>= 1) {
        if (tid < st) red[tid] += red[tid + st];
        __syncthreads();
    }
    float rstd = rsqrtf(red[0] * (1.0f / Dd) + 1e-5f);
#pragma unroll
    for (int i = 0; i < 4; i++) {
        int c = tid + i * 256;
        o[c]      = xr[c];
        o[Dd + c] = (h[i] - mu) * rstd * gamma[c] + beta[c];
    }
}

// ------------------------------- launcher -----------------------------------
extern "C" void kernel_launch(void* const* d_in, const int* in_sizes, int n_in,
                              void* d_out, int out_size)
{
    const float* x     = (const float*)d_in[0];
    const float* Wk    = (const float*)d_in[1];
    const float* bk    = (const float*)d_in[2];
    const float* Wq    = (const float*)d_in[3];
    const float* bq    = (const float*)d_in[4];
    const float* Wv    = (const float*)d_in[5];
    const float* bv    = (const float*)d_in[6];
    const float* gamma = (const float*)d_in[7];
    const float* beta  = (const float*)d_in[8];

    float* out = (float*)d_out;
    float* att = out + (long long)MT * 2 * Dd;
    float* wgt = att + (long long)MT * Dd;

    __half *x16, *W16, *QKV, *Vt, *w16;
    float* bqkv;
    cudaGetSymbolAddress((void**)&x16, g_x16);
    cudaGetSymbolAddress((void**)&W16, g_W16);
    cudaGetSymbolAddress((void**)&bqkv, g_b);
    cudaGetSymbolAddress((void**)&QKV, g_QKV);
    cudaGetSymbolAddress((void**)&Vt,  g_Vt);
    cudaGetSymbolAddress((void**)&w16, g_w16);

    cudaFuncSetAttribute(mma_gemm<0, false>, cudaFuncAttributeMaxDynamicSharedMemorySize, SMEM_BYTES);
    cudaFuncSetAttribute(mma_gemm<1, true>,  cudaFuncAttributeMaxDynamicSharedMemorySize, SMEM_BYTES);

    // 1) precision conversions
    cvt_x<<<MT * Dd / 4096, 1024>>>(x, x16);
    copy_bias<<<3, Dd>>>(bq, bk, bv, bqkv);
    {
        dim3 g(Dd / 32, Dd / 32, 3), b(32, 8);
        transW<<<g, b>>>(Wq, Wk, Wv, W16);
    }

    // 2) fused QKV projection: z in {Q,K,V}
    {
        dim3 g(Dd / BNm, MT / BMm, 3), b(256);
        mma_gemm<1, true><<<g, b, SMEM_BYTES>>>(x16, W16, bqkv, nullptr, QKV,
                                                Dd, Dd,
                                                0, (long long)Dd * Dd, (long long)MT * Dd,
                                                Dd, 1.0f);
    }

    // 3) V transpose per batch: [n,d] -> [d,n]
    {
        dim3 g(Dd / 32, Nn / 32, Bb), b(32, 8);
        transV<<<g, b>>>(QKV + (size_t)2 * MT * Dd, Vt);
    }

    // 4) scores = Q @ K^T / 32 -> wgt (fp32)
    {
        dim3 g(Nn / BNm, Nn / BMm, Bb), b(256);
        mma_gemm<0, false><<<g, b, SMEM_BYTES>>>(QKV, QKV + (size_t)MT * Dd, nullptr,
                                                 wgt, nullptr,
                                                 Dd, Nn,
                                                 (long long)Nn * Dd, (long long)Nn * Dd,
                                                 (long long)Nn * Nn, 0, 1.0f / 32.0f);
    }

    // 5) softmax rows in place + fp16 copy
    softmax_split<<<Bb * Nn, 256>>>(wgt, w16);

    // 6) att = weight @ V -> att (fp32)
    {
        dim3 g(Dd / BNm, Nn / BMm, Bb), b(256);
        mma_gemm<0, false><<<g, b, SMEM_BYTES>>>(w16, Vt, nullptr, att, nullptr,
                                                 Nn, Dd,
                                                 (long long)Nn * Nn, (long long)Nn * Dd,
                                                 (long long)Nn * Dd, 0, 1.0f);
    }

    // 7) out = concat(x, LN(x + att))
    ln_concat<<<Bb * Nn, 256>>>(x, att, gamma, beta, out);
}

// round 7
// speedup vs baseline: 6.6570x; 1.0698x over previous
#include <cuda_runtime.h>
#include <cuda_fp16.h>
#include <math.h>
#include <stdint.h>

// ---------------------------------------------------------------------------
// attention_83932250898666 : B=4, N=2048, D=1024
// d_out layout (float32):
//   [0, 16777216)        out   = concat(x, LN(x+att))   [B,N,2D]
//   [16777216, 25165824) att_score                      [B,N,D]
//   [25165824, 41943040) weight = softmax(QK^T/32)      [B,N,N]
// GEMMs: single-pass fp16 mma.sync (HMMA), fp32 accumulate.
// Round 7: rolling B-fragment prefetch + spread cp.async (full SW pipeline).
// ---------------------------------------------------------------------------

#define Bb 4
#define Nn 2048
#define Dd 1024
#define MT (Bb*Nn)   // 8192

// ------------------------- device scratch (no allocs) ----------------------
__device__ __half g_x16[(size_t)MT * Dd];
__device__ __half g_W16[(size_t)3 * Dd * Dd];      // [z][n][k] transposed weights
__device__ float  g_b[3 * Dd];                     // biases q,k,v
__device__ __half g_QKV[(size_t)3 * MT * Dd];      // Q | K | V
__device__ __half g_Vt[(size_t)MT * Dd];           // per-batch V^T [b][d][n]
__device__ __half g_w16[(size_t)Bb * Nn * Nn];     // softmax weights fp16

// ------------------------------ PTX helpers --------------------------------
__device__ __forceinline__ uint32_t smem_u32(const void* p) {
    uint32_t a;
    asm("{ .reg .u64 t; cvta.to.shared.u64 t, %1; cvt.u32.u64 %0, t; }" : "=r"(a) : "l"(p));
    return a;
}

#define CP16(dst, src) \
    asm volatile("cp.async.cg.shared.global [%0], [%1], 16;" :: "r"(dst), "l"(src))
#define CP_COMMIT() asm volatile("cp.async.commit_group;" ::: "memory")
#define CP_WAIT1()  asm volatile("cp.async.wait_group 1;" ::: "memory")

#define LDSM4(R0, R1, R2, R3, A) \
    asm volatile("ldmatrix.sync.aligned.m8n8.x4.shared.b16 {%0,%1,%2,%3}, [%4];" \
                 : "=r"(R0), "=r"(R1), "=r"(R2), "=r"(R3) : "r"(A))

#define MMAH(D, A0, A1, A2, A3, B0, B1) \
    asm volatile("mma.sync.aligned.m16n8k16.row.col.f32.f16.f16.f32 " \
                 "{%0,%1,%2,%3},{%4,%5,%6,%7},{%8,%9},{%0,%1,%2,%3};" \
                 : "+f"((D)[0]), "+f"((D)[1]), "+f"((D)[2]), "+f"((D)[3]) \
                 : "r"(A0), "r"(A1), "r"(A2), "r"(A3), "r"(B0), "r"(B1))

// ------------------------------- MMA GEMM ----------------------------------
// C[M,N] = alpha*(A @ Bmat^T)(+bias). A:[M,K] fp16 (ld=K), Bmat:[N,K] fp16 (ld=K).
// Block 128x128, 8 warps (4m x 2n), warp tile 32x64, K-chunk 64, 3-stage cp.async.
#define BMm 128
#define BNm 128
#define BKm 64
#define LDSm 72                          // padded row length in halves (144B)
#define OPA (128 * LDSm * 2)             // 18432 B
#define STGB (2 * OPA)                   // 36864 B
#define NSTAGE 3
#define SMEM_BYTES (NSTAGE * STGB)       // 110592

template<int EPI, bool BIAS>   // EPI 0: fp32 out ; EPI 1: fp16 out (+bias)
__global__ __launch_bounds__(256, 2)
void mma_gemm(const __half* __restrict__ A, const __half* __restrict__ B,
              const float* __restrict__ bias,
              float* __restrict__ Cf, __half* __restrict__ Ch,
              int K, int ldc,
              long long sA, long long sB, long long sC, long long sBias, float alpha)
{
    extern __shared__ char smem[];
    const uint32_t sbase = smem_u32(smem);
    const int tid  = threadIdx.x;
    const int wid  = tid >> 5;
    const int lane = tid & 31;
    const int wy = wid >> 1;            // 0..3  (m, 32 rows each)
    const int wx = wid & 1;             // 0..1  (n, 64 cols each)
    const int m0 = blockIdx.y * BMm;
    const int n0 = blockIdx.x * BNm;
    A += (long long)blockIdx.z * sA;
    B += (long long)blockIdx.z * sB;
    if (BIAS) bias += (long long)blockIdx.z * sBias;

    float acc[2][8][4];
#pragma unroll
    for (int i = 0; i < 2; i++)
#pragma unroll
        for (int j = 0; j < 8; j++)
#pragma unroll
            for (int q = 0; q < 4; q++) acc[i][j][q] = 0.0f;

    const int nch = K / BKm;

    // full-stage load (prologue only)
    auto load_stage = [&](int s, int k0) {
        uint32_t sb = sbase + s * STGB;
#pragma unroll
        for (int t = 0; t < 4; t++) {
            int idx = tid + 256 * t;
            int r = idx >> 3, c = idx & 7;
            CP16(sb + (uint32_t)(r * LDSm + c * 8) * 2,
                 A + (long long)(m0 + r) * K + k0 + c * 8);
        }
#pragma unroll
        for (int t = 0; t < 4; t++) {
            int idx = tid + 256 * t;
            int r = idx >> 3, c = idx & 7;
            CP16(sb + OPA + (uint32_t)(r * LDSm + c * 8) * 2,
                 B + (long long)(n0 + r) * K + k0 + c * 8);
        }
    };

    // 1/8th of a stage load (spread across mainloop slots); p in [0,8)
    auto load_part = [&](int s, int k0, int p) {
        uint32_t sb = sbase + s * STGB;
        if (p < 4) {
            int idx = tid + 256 * p;
            int r = idx >> 3, c = idx & 7;
            CP16(sb + (uint32_t)(r * LDSm + c * 8) * 2,
                 A + (long long)(m0 + r) * K + k0 + c * 8);
        } else {
            int idx = tid + 256 * (p - 4);
            int r = idx >> 3, c = idx & 7;
            CP16(sb + OPA + (uint32_t)(r * LDSm + c * 8) * 2,
                 B + (long long)(n0 + r) * K + k0 + c * 8);
        }
    };

    load_stage(0, 0);       CP_COMMIT();
    load_stage(1, BKm);     CP_COMMIT();

    // ldmatrix lane address components
    const int arow = (lane & 7) + ((lane >> 3) & 1) * 8;   // 0..15
    const int acol = (lane >> 4) * 8;                      // 0 / 8
    const int brow = (lane & 7) + (lane >> 4) * 8;
    const int bcol = ((lane >> 3) & 1) * 8;

    uint32_t af[2][2][4];      // A fragments, double buffered over ks
    uint32_t bf[2][4][2];      // B fragments, rolling buffer per half-ks (4 j each)

    auto ldA = [&](int buf, uint32_t sb, int ks) {
#pragma unroll
        for (int i = 0; i < 2; i++) {
            uint32_t aoff = (uint32_t)((32 * wy + 16 * i + arow) * LDSm
                                       + ks * 16 + acol) * 2;
            LDSM4(af[buf][i][0], af[buf][i][1], af[buf][i][2], af[buf][i][3], sb + aoff);
        }
    };
    // loads 4 j-tiles (half the warp's 8) for a given (ks, jh)
    auto ldB = [&](int buf, uint32_t sb, int ks, int jh) {
#pragma unroll
        for (int jpp = 0; jpp < 2; jpp++) {
            uint32_t boff = (uint32_t)((64 * wx + 16 * (2 * jh + jpp) + brow) * LDSm
                                       + ks * 16 + bcol) * 2;
            LDSM4(bf[buf][2*jpp][0], bf[buf][2*jpp][1], bf[buf][2*jpp+1][0], bf[buf][2*jpp+1][1],
                  sb + OPA + boff);
        }
    };

    for (int c = 0; c < nch; c++) {
        CP_WAIT1();
        __syncthreads();
        const uint32_t sb = sbase + (c % NSTAGE) * STGB;
        const bool pf = (c + 2 < nch);
        const int s2 = (c + 2) % NSTAGE;
        const int k2 = (c + 2) * BKm;

        ldA(0, sb, 0);
        ldB(0, sb, 0, 0);
#pragma unroll
        for (int idx = 0; idx < 8; idx++) {          // ks = idx>>1, jh = idx&1
            const int ks = idx >> 1, jh = idx & 1;
            if (idx < 7) ldB((idx + 1) & 1, sb, (idx + 1) >> 1, (idx + 1) & 1);
            if (jh == 0 && ks < 3) ldA((ks + 1) & 1, sb, ks + 1);
            if (pf) load_part(s2, k2, idx);
            const int ab = ks & 1, bb = idx & 1;
#pragma unroll
            for (int i = 0; i < 2; i++)
#pragma unroll
                for (int jj = 0; jj < 4; jj++)
                    MMAH(acc[i][jh * 4 + jj],
                         af[ab][i][0], af[ab][i][1], af[ab][i][2], af[ab][i][3],
                         bf[bb][jj][0], bf[bb][jj][1]);
        }
        CP_COMMIT();
    }

    // ------------------------------ epilogue --------------------------------
    const int g  = lane >> 2;
    const int t4 = lane & 3;
    const long long cb = (long long)blockIdx.z * sC;
#pragma unroll
    for (int i = 0; i < 2; i++) {
#pragma unroll
        for (int j = 0; j < 8; j++) {
            int mrow = m0 + 32 * wy + 16 * i + g;
            int ncol = n0 + 64 * wx + 8 * j + 2 * t4;
            float v00 = acc[i][j][0] * alpha, v01 = acc[i][j][1] * alpha;
            float v10 = acc[i][j][2] * alpha, v11 = acc[i][j][3] * alpha;
            long long o0 = cb + (long long)mrow * ldc + ncol;
            long long o1 = cb + (long long)(mrow + 8) * ldc + ncol;
            if (EPI == 0) {
                *(float2*)(Cf + o0) = make_float2(v00, v01);
                *(float2*)(Cf + o1) = make_float2(v10, v11);
            } else {
                if (BIAS) {
                    float b0 = bias[ncol], b1 = bias[ncol + 1];
                    v00 += b0; v01 += b1; v10 += b0; v11 += b1;
                }
                *(__half2*)(Ch + o0) = __floats2half2_rn(v00, v01);
                *(__half2*)(Ch + o1) = __floats2half2_rn(v10, v11);
            }
        }
    }
}

// --------------------------- aux kernels ------------------------------------
// fp32 -> fp16, 4 elts/thread
__global__ void cvt_x(const float* __restrict__ in, __half* __restrict__ out)
{
    long long i = ((long long)blockIdx.x * blockDim.x + threadIdx.x) * 4;
    float4 v = *(const float4*)(in + i);
    *(__half2*)(out + i)     = __floats2half2_rn(v.x, v.y);
    *(__half2*)(out + i + 2) = __floats2half2_rn(v.z, v.w);
}

__global__ void copy_bias(const float* __restrict__ b0, const float* __restrict__ b1,
                          const float* __restrict__ b2, float* __restrict__ dst)
{
    int z = blockIdx.x;
    const float* s = (z == 0) ? b0 : (z == 1) ? b1 : b2;
    dst[z * Dd + threadIdx.x] = s[threadIdx.x];
}

// Wt[n,k] = W[k,n] fp16 ; z selects which W
__global__ void transW(const float* __restrict__ W0, const float* __restrict__ W1,
                       const float* __restrict__ W2, __half* __restrict__ out)
{
    __shared__ float t[32][33];
    const float* W = (blockIdx.z == 0) ? W0 : (blockIdx.z == 1) ? W1 : W2;
    __half* o = out + (size_t)blockIdx.z * Dd * Dd;
    int bx = blockIdx.x * 32, by = blockIdx.y * 32;
    int tx = threadIdx.x, ty = threadIdx.y;
#pragma unroll
    for (int r = 0; r < 4; r++)
        t[ty + 8 * r][tx] = W[(long long)(by + ty + 8 * r) * Dd + bx + tx];
    __syncthreads();
#pragma unroll
    for (int r = 0; r < 4; r++)
        o[(long long)(bx + ty + 8 * r) * Dd + by + tx] = __float2half_rn(t[tx][ty + 8 * r]);
}

// per-batch fp16 transpose: in [2048,1024] -> out [1024,2048]
__global__ void transV(const __half* __restrict__ in, __half* __restrict__ out)
{
    __shared__ __half t[32][34];
    long long zi = (long long)blockIdx.z * Nn * Dd;
    int bx = blockIdx.x * 32, by = blockIdx.y * 32;
    int tx = threadIdx.x, ty = threadIdx.y;
#pragma unroll
    for (int r = 0; r < 4; r++)
        t[ty + 8 * r][tx] = in[zi + (long long)(by + ty + 8 * r) * Dd + bx + tx];
    __syncthreads();
#pragma unroll
    for (int r = 0; r < 4; r++)
        out[zi + (long long)(bx + ty + 8 * r) * Nn + by + tx] = t[tx][ty + 8 * r];
}

// in-place row softmax + fp16 emission
__global__ void softmax_split(float* __restrict__ W, __half* __restrict__ wh)
{
    long long row = blockIdx.x;
    float* p = W + row * (long long)Nn;
    __half* ph = wh + row * (long long)Nn;
    __shared__ float red[256];
    int tid = threadIdx.x;

    float mx = -INFINITY;
#pragma unroll
    for (int i = 0; i < 8; i++) mx = fmaxf(mx, p[tid + i * 256]);
    red[tid] = mx; __syncthreads();
#pragma unroll
    for (int s = 128; s > 0; s >>= 1) {
        if (tid < s) red[tid] = fmaxf(red[tid], red[tid + s]);
        __syncthreads();
    }
    mx = red[0]; __syncthreads();

    float e[8], sum = 0.0f;
#pragma unroll
    for (int i = 0; i < 8; i++) { e[i] = expf(p[tid + i * 256] - mx); sum += e[i]; }
    red[tid] = sum; __syncthreads();
#pragma unroll
    for (int s = 128; s > 0; s >>= 1) {
        if (tid < s) red[tid] += red[tid + s];
        __syncthreads();
    }
    float inv = 1.0f / red[0];
#pragma unroll
    for (int i = 0; i < 8; i++) {
        int c = tid + i * 256;
        float v = e[i] * inv;
        p[c] = v;
        ph[c] = __float2half_rn(v);
    }
}

// residual + layernorm + concat(x, ln)
__global__ void ln_concat(const float* __restrict__ x, const float* __restrict__ att,
                          const float* __restrict__ gamma, const float* __restrict__ beta,
                          float* __restrict__ out)
{
    long long row = blockIdx.x;
    const float* xr = x + row * Dd;
    const float* ar = att + row * Dd;
    float* o = out + row * (2 * Dd);
    __shared__ float red[256];
    int tid = threadIdx.x;

    float h[4], s = 0.0f;
#pragma unroll
    for (int i = 0; i < 4; i++) { int c = tid + i * 256; h[i] = xr[c] + ar[c]; s += h[i]; }
    red[tid] = s; __syncthreads();
#pragma unroll
    for (int st = 128; st > 0; st >>= 1) {
        if (tid < st) red[tid] += red[tid + st];
        __syncthreads();
    }
    float mu = red[0] * (1.0f / Dd); __syncthreads();

    float v = 0.0f;
#pragma unroll
    for (int i = 0; i < 4; i++) { float d = h[i] - mu; v += d * d; }
    red[tid] = v; __syncthreads();
#pragma unroll
    for (int st = 128; st > 0; st >>= 1) {
        if (tid < st) red[tid] += red[tid + st];
        __syncthreads();
    }
    float rstd = rsqrtf(red[0] * (1.0f / Dd) + 1e-5f);
#pragma unroll
    for (int i = 0; i < 4; i++) {
        int c = tid + i * 256;
        o[c]      = xr[c];
        o[Dd + c] = (h[i] - mu) * rstd * gamma[c] + beta[c];
    }
}

// ------------------------------- launcher -----------------------------------
extern "C" void kernel_launch(void* const* d_in, const int* in_sizes, int n_in,
                              void* d_out, int out_size)
{
    const float* x     = (const float*)d_in[0];
    const float* Wk    = (const float*)d_in[1];
    const float* bk    = (const float*)d_in[2];
    const float* Wq    = (const float*)d_in[3];
    const float* bq    = (const float*)d_in[4];
    const float* Wv    = (const float*)d_in[5];
    const float* bv    = (const float*)d_in[6];
    const float* gamma = (const float*)d_in[7];
    const float* beta  = (const float*)d_in[8];

    float* out = (float*)d_out;
    float* att = out + (long long)MT * 2 * Dd;
    float* wgt = att + (long long)MT * Dd;

    __half *x16, *W16, *QKV, *Vt, *w16;
    float* bqkv;
    cudaGetSymbolAddress((void**)&x16, g_x16);
    cudaGetSymbolAddress((void**)&W16, g_W16);
    cudaGetSymbolAddress((void**)&bqkv, g_b);
    cudaGetSymbolAddress((void**)&QKV, g_QKV);
    cudaGetSymbolAddress((void**)&Vt,  g_Vt);
    cudaGetSymbolAddress((void**)&w16, g_w16);

    cudaFuncSetAttribute(mma_gemm<0, false>, cudaFuncAttributeMaxDynamicSharedMemorySize, SMEM_BYTES);
    cudaFuncSetAttribute(mma_gemm<1, true>,  cudaFuncAttributeMaxDynamicSharedMemorySize, SMEM_BYTES);

    // 1) precision conversions
    cvt_x<<<MT * Dd / 4096, 1024>>>(x, x16);
    copy_bias<<<3, Dd>>>(bq, bk, bv, bqkv);
    {
        dim3 g(Dd / 32, Dd / 32, 3), b(32, 8);
        transW<<<g, b>>>(Wq, Wk, Wv, W16);
    }

    // 2) fused QKV projection: z in {Q,K,V}
    {
        dim3 g(Dd / BNm, MT / BMm, 3), b(256);
        mma_gemm<1, true><<<g, b, SMEM_BYTES>>>(x16, W16, bqkv, nullptr, QKV,
                                                Dd, Dd,
                                                0, (long long)Dd * Dd, (long long)MT * Dd,
                                                Dd, 1.0f);
    }

    // 3) V transpose per batch: [n,d] -> [d,n]
    {
        dim3 g(Dd / 32, Nn / 32, Bb), b(32, 8);
        transV<<<g, b>>>(QKV + (size_t)2 * MT * Dd, Vt);
    }

    // 4) scores = Q @ K^T / 32 -> wgt (fp32)
    {
        dim3 g(Nn / BNm, Nn / BMm, Bb), b(256);
        mma_gemm<0, false><<<g, b, SMEM_BYTES>>>(QKV, QKV + (size_t)MT * Dd, nullptr,
                                                 wgt, nullptr,
                                                 Dd, Nn,
                                                 (long long)Nn * Dd, (long long)Nn * Dd,
                                                 (long long)Nn * Nn, 0, 1.0f / 32.0f);
    }

    // 5) softmax rows in place + fp16 copy
    softmax_split<<<Bb * Nn, 256>>>(wgt, w16);

    // 6) att = weight @ V -> att (fp32)
    {
        dim3 g(Dd / BNm, Nn / BMm, Bb), b(256);
        mma_gemm<0, false><<<g, b, SMEM_BYTES>>>(w16, Vt, nullptr, att, nullptr,
                                                 Nn, Dd,
                                                 (long long)Nn * Nn, (long long)Nn * Dd,
                                                 (long long)Nn * Dd, 0, 1.0f);
    }

    // 7) out = concat(x, LN(x + att))
    ln_concat<<<Bb * Nn, 256>>>(x, att, gamma, beta, out);
}

// round 8
// speedup vs baseline: 6.7180x; 1.0092x over previous
#include <cuda_runtime.h>
#include <cuda_fp16.h>
#include <math.h>
#include <stdint.h>

// ---------------------------------------------------------------------------
// attention_83932250898666 : B=4, N=2048, D=1024
// d_out layout (float32):
//   [0, 16777216)        out   = concat(x, LN(x+att))   [B,N,2D]
//   [16777216, 25165824) att_score                      [B,N,D]
//   [25165824, 41943040) weight = softmax(QK^T/32)      [B,N,N]
// GEMMs: single-pass fp16 mma.sync (HMMA), fp32 accumulate.
// Round 8: block 128x256, warp 64x64, rolling fragment pipeline, 1 CTA/SM.
// ---------------------------------------------------------------------------

#define Bb 4
#define Nn 2048
#define Dd 1024
#define MT (Bb*Nn)   // 8192

// ------------------------- device scratch (no allocs) ----------------------
__device__ __half g_x16[(size_t)MT * Dd];
__device__ __half g_W16[(size_t)3 * Dd * Dd];      // [z][n][k] transposed weights
__device__ float  g_b[3 * Dd];                     // biases q,k,v
__device__ __half g_QKV[(size_t)3 * MT * Dd];      // Q | K | V
__device__ __half g_Vt[(size_t)MT * Dd];           // per-batch V^T [b][d][n]
__device__ __half g_w16[(size_t)Bb * Nn * Nn];     // softmax weights fp16

// ------------------------------ PTX helpers --------------------------------
__device__ __forceinline__ uint32_t smem_u32(const void* p) {
    uint32_t a;
    asm("{ .reg .u64 t; cvta.to.shared.u64 t, %1; cvt.u32.u64 %0, t; }" : "=r"(a) : "l"(p));
    return a;
}

#define CP16(dst, src) \
    asm volatile("cp.async.cg.shared.global [%0], [%1], 16;" :: "r"(dst), "l"(src))
#define CP_COMMIT() asm volatile("cp.async.commit_group;" ::: "memory")
#define CP_WAIT1()  asm volatile("cp.async.wait_group 1;" ::: "memory")

#define LDSM4(R0, R1, R2, R3, A) \
    asm volatile("ldmatrix.sync.aligned.m8n8.x4.shared.b16 {%0,%1,%2,%3}, [%4];" \
                 : "=r"(R0), "=r"(R1), "=r"(R2), "=r"(R3) : "r"(A))

#define MMAH(D, A0, A1, A2, A3, B0, B1) \
    asm volatile("mma.sync.aligned.m16n8k16.row.col.f32.f16.f16.f32 " \
                 "{%0,%1,%2,%3},{%4,%5,%6,%7},{%8,%9},{%0,%1,%2,%3};" \
                 : "+f"((D)[0]), "+f"((D)[1]), "+f"((D)[2]), "+f"((D)[3]) \
                 : "r"(A0), "r"(A1), "r"(A2), "r"(A3), "r"(B0), "r"(B1))

// ------------------------------- MMA GEMM ----------------------------------
// C[M,N] = alpha*(A @ Bmat^T)(+bias). A:[M,K] fp16 (ld=K), Bmat:[N,K] fp16 (ld=K).
// Block 128x256, 8 warps (2m x 4n), warp tile 64x64, K-chunk 64, 3-stage cp.async.
#define BMm 128
#define BNm 256
#define BKm 64
#define LDSm 72                          // padded row length in halves (144B)
#define OPA (128 * LDSm * 2)             // 18432 B
#define OPBB (256 * LDSm * 2)            // 36864 B
#define STGB (OPA + OPBB)                // 55296 B
#define NSTAGE 3
#define SMEM_BYTES (NSTAGE * STGB)       // 165888

template<int EPI, bool BIAS>   // EPI 0: fp32 out ; EPI 1: fp16 out (+bias)
__global__ __launch_bounds__(256, 1)
void mma_gemm(const __half* __restrict__ A, const __half* __restrict__ B,
              const float* __restrict__ bias,
              float* __restrict__ Cf, __half* __restrict__ Ch,
              int K, int ldc,
              long long sA, long long sB, long long sC, long long sBias, float alpha)
{
    extern __shared__ char smem[];
    const uint32_t sbase = smem_u32(smem);
    const int tid  = threadIdx.x;
    const int wid  = tid >> 5;
    const int lane = tid & 31;
    const int wy = wid >> 2;            // 0..1  (m, 64 rows each)
    const int wx = wid & 3;             // 0..3  (n, 64 cols each)
    const int m0 = blockIdx.y * BMm;
    const int n0 = blockIdx.x * BNm;
    A += (long long)blockIdx.z * sA;
    B += (long long)blockIdx.z * sB;
    if (BIAS) bias += (long long)blockIdx.z * sBias;

    float acc[4][8][4];
#pragma unroll
    for (int i = 0; i < 4; i++)
#pragma unroll
        for (int j = 0; j < 8; j++)
#pragma unroll
            for (int q = 0; q < 4; q++) acc[i][j][q] = 0.0f;

    const int nch = K / BKm;

    // full-stage load (prologue only): A 4 parts + B 8 parts
    auto load_stage = [&](int s, int k0) {
        uint32_t sb = sbase + s * STGB;
#pragma unroll
        for (int t = 0; t < 4; t++) {
            int idx = tid + 256 * t;
            int r = idx >> 3, c = idx & 7;
            CP16(sb + (uint32_t)(r * LDSm + c * 8) * 2,
                 A + (long long)(m0 + r) * K + k0 + c * 8);
        }
#pragma unroll
        for (int t = 0; t < 8; t++) {
            int idx = tid + 256 * t;
            int r = idx >> 3, c = idx & 7;
            CP16(sb + OPA + (uint32_t)(r * LDSm + c * 8) * 2,
                 B + (long long)(n0 + r) * K + k0 + c * 8);
        }
    };

    // spread load: slot p in [0,8): slots 0-3 carry 1 A part + 1 B part, 4-7 B only
    auto load_part = [&](int s, int k0, int p) {
        uint32_t sb = sbase + s * STGB;
        if (p < 4) {
            int idx = tid + 256 * p;
            int r = idx >> 3, c = idx & 7;
            CP16(sb + (uint32_t)(r * LDSm + c * 8) * 2,
                 A + (long long)(m0 + r) * K + k0 + c * 8);
        }
        {
            int idx = tid + 256 * p;
            int r = idx >> 3, c = idx & 7;
            CP16(sb + OPA + (uint32_t)(r * LDSm + c * 8) * 2,
                 B + (long long)(n0 + r) * K + k0 + c * 8);
        }
    };

    load_stage(0, 0);       CP_COMMIT();
    load_stage(1, BKm);     CP_COMMIT();

    // ldmatrix lane address components
    const int arow = (lane & 7) + ((lane >> 3) & 1) * 8;   // 0..15
    const int acol = (lane >> 4) * 8;                      // 0 / 8
    const int brow = (lane & 7) + (lane >> 4) * 8;
    const int bcol = ((lane >> 3) & 1) * 8;

    uint32_t af[2][4][4];      // A fragments (64 rows = 4 i-tiles), dbuf over ks
    uint32_t bf[2][4][2];      // B fragments, rolling buffer per half-ks (4 j each)

    auto ldA = [&](int buf, uint32_t sb, int ks) {
#pragma unroll
        for (int i = 0; i < 4; i++) {
            uint32_t aoff = (uint32_t)((64 * wy + 16 * i + arow) * LDSm
                                       + ks * 16 + acol) * 2;
            LDSM4(af[buf][i][0], af[buf][i][1], af[buf][i][2], af[buf][i][3], sb + aoff);
        }
    };
    // loads 4 j-tiles (half the warp's 8) for a given (ks, jh)
    auto ldB = [&](int buf, uint32_t sb, int ks, int jh) {
#pragma unroll
        for (int jpp = 0; jpp < 2; jpp++) {
            uint32_t boff = (uint32_t)((64 * wx + 16 * (2 * jh + jpp) + brow) * LDSm
                                       + ks * 16 + bcol) * 2;
            LDSM4(bf[buf][2*jpp][0], bf[buf][2*jpp][1], bf[buf][2*jpp+1][0], bf[buf][2*jpp+1][1],
                  sb + OPA + boff);
        }
    };

    for (int c = 0; c < nch; c++) {
        CP_WAIT1();
        __syncthreads();
        const uint32_t sb = sbase + (c % NSTAGE) * STGB;
        const bool pf = (c + 2 < nch);
        const int s2 = (c + 2) % NSTAGE;
        const int k2 = (c + 2) * BKm;

        ldA(0, sb, 0);
        ldB(0, sb, 0, 0);
#pragma unroll
        for (int idx = 0; idx < 8; idx++) {          // ks = idx>>1, jh = idx&1
            const int ks = idx >> 1, jh = idx & 1;
            if (idx < 7) ldB((idx + 1) & 1, sb, (idx + 1) >> 1, (idx + 1) & 1);
            if (jh == 0 && ks < 3) ldA((ks + 1) & 1, sb, ks + 1);
            if (pf) load_part(s2, k2, idx);
            const int ab = ks & 1, bb = idx & 1;
#pragma unroll
            for (int i = 0; i < 4; i++)
#pragma unroll
                for (int jj = 0; jj < 4; jj++)
                    MMAH(acc[i][jh * 4 + jj],
                         af[ab][i][0], af[ab][i][1], af[ab][i][2], af[ab][i][3],
                         bf[bb][jj][0], bf[bb][jj][1]);
        }
        CP_COMMIT();
    }

    // ------------------------------ epilogue --------------------------------
    const int g  = lane >> 2;
    const int t4 = lane & 3;
    const long long cb = (long long)blockIdx.z * sC;
#pragma unroll
    for (int i = 0; i < 4; i++) {
#pragma unroll
        for (int j = 0; j < 8; j++) {
            int mrow = m0 + 64 * wy + 16 * i + g;
            int ncol = n0 + 64 * wx + 8 * j + 2 * t4;
            float v00 = acc[i][j][0] * alpha, v01 = acc[i][j][1] * alpha;
            float v10 = acc[i][j][2] * alpha, v11 = acc[i][j][3] * alpha;
            long long o0 = cb + (long long)mrow * ldc + ncol;
            long long o1 = cb + (long long)(mrow + 8) * ldc + ncol;
            if (EPI == 0) {
                *(float2*)(Cf + o0) = make_float2(v00, v01);
                *(float2*)(Cf + o1) = make_float2(v10, v11);
            } else {
                if (BIAS) {
                    float b0 = bias[ncol], b1 = bias[ncol + 1];
                    v00 += b0; v01 += b1; v10 += b0; v11 += b1;
                }
                *(__half2*)(Ch + o0) = __floats2half2_rn(v00, v01);
                *(__half2*)(Ch + o1) = __floats2half2_rn(v10, v11);
            }
        }
    }
}

// --------------------------- aux kernels ------------------------------------
// fp32 -> fp16, 4 elts/thread
__global__ void cvt_x(const float* __restrict__ in, __half* __restrict__ out)
{
    long long i = ((long long)blockIdx.x * blockDim.x + threadIdx.x) * 4;
    float4 v = *(const float4*)(in + i);
    *(__half2*)(out + i)     = __floats2half2_rn(v.x, v.y);
    *(__half2*)(out + i + 2) = __floats2half2_rn(v.z, v.w);
}

__global__ void copy_bias(const float* __restrict__ b0, const float* __restrict__ b1,
                          const float* __restrict__ b2, float* __restrict__ dst)
{
    int z = blockIdx.x;
    const float* s = (z == 0) ? b0 : (z == 1) ? b1 : b2;
    dst[z * Dd + threadIdx.x] = s[threadIdx.x];
}

// Wt[n,k] = W[k,n] fp16 ; z selects which W
__global__ void transW(const float* __restrict__ W0, const float* __restrict__ W1,
                       const float* __restrict__ W2, __half* __restrict__ out)
{
    __shared__ float t[32][33];
    const float* W = (blockIdx.z == 0) ? W0 : (blockIdx.z == 1) ? W1 : W2;
    __half* o = out + (size_t)blockIdx.z * Dd * Dd;
    int bx = blockIdx.x * 32, by = blockIdx.y * 32;
    int tx = threadIdx.x, ty = threadIdx.y;
#pragma unroll
    for (int r = 0; r < 4; r++)
        t[ty + 8 * r][tx] = W[(long long)(by + ty + 8 * r) * Dd + bx + tx];
    __syncthreads();
#pragma unroll
    for (int r = 0; r < 4; r++)
        o[(long long)(bx + ty + 8 * r) * Dd + by + tx] = __float2half_rn(t[tx][ty + 8 * r]);
}

// per-batch fp16 transpose: in [2048,1024] -> out [1024,2048]
__global__ void transV(const __half* __restrict__ in, __half* __restrict__ out)
{
    __shared__ __half t[32][34];
    long long zi = (long long)blockIdx.z * Nn * Dd;
    int bx = blockIdx.x * 32, by = blockIdx.y * 32;
    int tx = threadIdx.x, ty = threadIdx.y;
#pragma unroll
    for (int r = 0; r < 4; r++)
        t[ty + 8 * r][tx] = in[zi + (long long)(by + ty + 8 * r) * Dd + bx + tx];
    __syncthreads();
#pragma unroll
    for (int r = 0; r < 4; r++)
        out[zi + (long long)(bx + ty + 8 * r) * Nn + by + tx] = t[tx][ty + 8 * r];
}

// single-read row softmax: values held in registers; writes fp32 + fp16
__global__ void softmax_split(float* __restrict__ W, __half* __restrict__ wh)
{
    long long row = blockIdx.x;
    float* p = W + row * (long long)Nn;
    __half* ph = wh + row * (long long)Nn;
    __shared__ float red[8];
    const int tid = threadIdx.x;
    const int lane = tid & 31, warp = tid >> 5;

    float e[8];
    {
        float4 v0 = *(const float4*)(p + tid * 8);
        float4 v1 = *(const float4*)(p + tid * 8 + 4);
        e[0]=v0.x; e[1]=v0.y; e[2]=v0.z; e[3]=v0.w;
        e[4]=v1.x; e[5]=v1.y; e[6]=v1.z; e[7]=v1.w;
    }
    float mx = e[0];
#pragma unroll
    for (int i = 1; i < 8; i++) mx = fmaxf(mx, e[i]);
#pragma unroll
    for (int s = 16; s > 0; s >>= 1)
        mx = fmaxf(mx, __shfl_xor_sync(0xffffffffu, mx, s));
    if (lane == 0) red[warp] = mx;
    __syncthreads();
    mx = red[0];
#pragma unroll
    for (int w = 1; w < 8; w++) mx = fmaxf(mx, red[w]);
    __syncthreads();

    float sum = 0.0f;
#pragma unroll
    for (int i = 0; i < 8; i++) { e[i] = expf(e[i] - mx); sum += e[i]; }
#pragma unroll
    for (int s = 16; s > 0; s >>= 1)
        sum += __shfl_xor_sync(0xffffffffu, sum, s);
    if (lane == 0) red[warp] = sum;
    __syncthreads();
    sum = red[0];
#pragma unroll
    for (int w = 1; w < 8; w++) sum += red[w];
    float inv = 1.0f / sum;

    float4 o0, o1;
    o0.x = e[0]*inv; o0.y = e[1]*inv; o0.z = e[2]*inv; o0.w = e[3]*inv;
    o1.x = e[4]*inv; o1.y = e[5]*inv; o1.z = e[6]*inv; o1.w = e[7]*inv;
    *(float4*)(p + tid * 8)     = o0;
    *(float4*)(p + tid * 8 + 4) = o1;
    __half2 h0 = __floats2half2_rn(o0.x, o0.y);
    __half2 h1 = __floats2half2_rn(o0.z, o0.w);
    __half2 h2 = __floats2half2_rn(o1.x, o1.y);
    __half2 h3 = __floats2half2_rn(o1.z, o1.w);
    *(__half2*)(ph + tid * 8)     = h0;
    *(__half2*)(ph + tid * 8 + 2) = h1;
    *(__half2*)(ph + tid * 8 + 4) = h2;
    *(__half2*)(ph + tid * 8 + 6) = h3;
}

// residual + layernorm + concat(x, ln)
__global__ void ln_concat(const float* __restrict__ x, const float* __restrict__ att,
                          const float* __restrict__ gamma, const float* __restrict__ beta,
                          float* __restrict__ out)
{
    long long row = blockIdx.x;
    const float* xr = x + row * Dd;
    const float* ar = att + row * Dd;
    float* o = out + row * (2 * Dd);
    __shared__ float red[256];
    int tid = threadIdx.x;

    float h[4], s = 0.0f;
#pragma unroll
    for (int i = 0; i < 4; i++) { int c = tid + i * 256; h[i] = xr[c] + ar[c]; s += h[i]; }
    red[tid] = s; __syncthreads();
#pragma unroll
    for (int st = 128; st > 0; st >>= 1) {
        if (tid < st) red[tid] += red[tid + st];
        __syncthreads();
    }
    float mu = red[0] * (1.0f / Dd); __syncthreads();

    float v = 0.0f;
#pragma unroll
    for (int i = 0; i < 4; i++) { float d = h[i] - mu; v += d * d; }
    red[tid] = v; __syncthreads();
#pragma unroll
    for (int st = 128; st > 0; st >>= 1) {
        if (tid < st) red[tid] += red[tid + st];
        __syncthreads();
    }
    float rstd = rsqrtf(red[0] * (1.0f / Dd) + 1e-5f);
#pragma unroll
    for (int i = 0; i < 4; i++) {
        int c = tid + i * 256;
        o[c]      = xr[c];
        o[Dd + c] = (h[i] - mu) * rstd * gamma[c] + beta[c];
    }
}

// ------------------------------- launcher -----------------------------------
extern "C" void kernel_launch(void* const* d_in, const int* in_sizes, int n_in,
                              void* d_out, int out_size)
{
    const float* x     = (const float*)d_in[0];
    const float* Wk    = (const float*)d_in[1];
    const float* bk    = (const float*)d_in[2];
    const float* Wq    = (const float*)d_in[3];
    const float* bq    = (const float*)d_in[4];
    const float* Wv    = (const float*)d_in[5];
    const float* bv    = (const float*)d_in[6];
    const float* gamma = (const float*)d_in[7];
    const float* beta  = (const float*)d_in[8];

    float* out = (float*)d_out;
    float* att = out + (long long)MT * 2 * Dd;
    float* wgt = att + (long long)MT * Dd;

    __half *x16, *W16, *QKV, *Vt, *w16;
    float* bqkv;
    cudaGetSymbolAddress((void**)&x16, g_x16);
    cudaGetSymbolAddress((void**)&W16, g_W16);
    cudaGetSymbolAddress((void**)&bqkv, g_b);
    cudaGetSymbolAddress((void**)&QKV, g_QKV);
    cudaGetSymbolAddress((void**)&Vt,  g_Vt);
    cudaGetSymbolAddress((void**)&w16, g_w16);

    cudaFuncSetAttribute(mma_gemm<0, false>, cudaFuncAttributeMaxDynamicSharedMemorySize, SMEM_BYTES);
    cudaFuncSetAttribute(mma_gemm<1, true>,  cudaFuncAttributeMaxDynamicSharedMemorySize, SMEM_BYTES);

    // 1) precision conversions
    cvt_x<<<MT * Dd / 4096, 1024>>>(x, x16);
    copy_bias<<<3, Dd>>>(bq, bk, bv, bqkv);
    {
        dim3 g(Dd / 32, Dd / 32, 3), b(32, 8);
        transW<<<g, b>>>(Wq, Wk, Wv, W16);
    }

    // 2) fused QKV projection: z in {Q,K,V}
    {
        dim3 g(Dd / BNm, MT / BMm, 3), b(256);
        mma_gemm<1, true><<<g, b, SMEM_BYTES>>>(x16, W16, bqkv, nullptr, QKV,
                                                Dd, Dd,
                                                0, (long long)Dd * Dd, (long long)MT * Dd,
                                                Dd, 1.0f);
    }

    // 3) V transpose per batch: [n,d] -> [d,n]
    {
        dim3 g(Dd / 32, Nn / 32, Bb), b(32, 8);
        transV<<<g, b>>>(QKV + (size_t)2 * MT * Dd, Vt);
    }

    // 4) scores = Q @ K^T / 32 -> wgt (fp32)
    {
        dim3 g(Nn / BNm, Nn / BMm, Bb), b(256);
        mma_gemm<0, false><<<g, b, SMEM_BYTES>>>(QKV, QKV + (size_t)MT * Dd, nullptr,
                                                 wgt, nullptr,
                                                 Dd, Nn,
                                                 (long long)Nn * Dd, (long long)Nn * Dd,
                                                 (long long)Nn * Nn, 0, 1.0f / 32.0f);
    }

    // 5) softmax rows in place + fp16 copy (single gmem read)
    softmax_split<<<Bb * Nn, 256>>>(wgt, w16);

    // 6) att = weight @ V -> att (fp32)
    {
        dim3 g(Dd / BNm, Nn / BMm, Bb), b(256);
        mma_gemm<0, false><<<g, b, SMEM_BYTES>>>(w16, Vt, nullptr, att, nullptr,
                                                 Nn, Dd,
                                                 (long long)Nn * Nn, (long long)Nn * Dd,
                                                 (long long)Nn * Dd, 0, 1.0f);
    }

    // 7) out = concat(x, LN(x + att))
    ln_concat<<<Bb * Nn, 256>>>(x, att, gamma, beta, out);
}